// round 2
// baseline (speedup 1.0000x reference)
#include <cuda_runtime.h>
#include <math.h>

#define BSZ 64
#define TT  256
#define FF  256
#define UU  1024
#define GG  3072          // 3*U
#define MIN_ (BSZ*TT)     // 16384 rows for the input projection GEMM

#define NBLK 144          // persistent grid: 48 N-tiles x 3 K-slices (< 148 SMs)

// ---------------- scratch (static device memory; no allocations) -------------
__device__ float g_gx[(size_t)MIN_ * GG];     // per-layer input projections
__device__ float g_y0[(size_t)MIN_ * UU];     // layer0 output
__device__ float g_y1[(size_t)MIN_ * UU];     // layer1 output
__device__ float g_rec[3 * BSZ * GG];         // split-K partials of h @ Ur
__device__ float g_h[3 * BSZ * UU];           // running hidden states

__device__ unsigned g_bar_count = 0;
__device__ unsigned g_bar_phase = 0;

// ---------------- software grid barrier (all NBLK blocks co-resident) --------
__device__ __forceinline__ void grid_sync()
{
    __syncthreads();
    if (threadIdx.x == 0) {
        __threadfence();
        unsigned gen = atomicAdd(&g_bar_phase, 0u);
        unsigned arrived = atomicAdd(&g_bar_count, 1u);
        if (arrived == NBLK - 1) {
            g_bar_count = 0;
            __threadfence();
            atomicExch(&g_bar_phase, gen + 1u);
        } else {
            while (atomicAdd(&g_bar_phase, 0u) == gen) { __nanosleep(32); }
        }
        __threadfence();
    }
    __syncthreads();
}

// ---------------- generic tiled fp32 GEMM with bias (input projections) ------
template<int BM,int BN,int BK,int TM,int TN>
__launch_bounds__(256)
__global__ void gemm_bias(const float* __restrict__ A,
                          const float* __restrict__ Bm,
                          const float* __restrict__ bias,
                          float* __restrict__ C,
                          int M, int N, int K)
{
    constexpr int TX = BN / TN;
    constexpr int TY = BM / TM;
    static_assert(TX * TY == 256, "bad tile config");

    __shared__ float As[BK][BM + 4];
    __shared__ float Bs[BK][BN];

    const int tid  = threadIdx.x;
    const int tx   = tid % TX;
    const int ty   = tid / TX;
    const int row0 = blockIdx.y * BM;
    const int col0 = blockIdx.x * BN;

    float acc[TM][TN];
    #pragma unroll
    for (int i = 0; i < TM; i++)
        #pragma unroll
        for (int j = 0; j < TN; j++) acc[i][j] = 0.f;

    for (int k0 = 0; k0 < K; k0 += BK) {
        for (int i = tid; i < BM * (BK / 4); i += 256) {
            int m  = i / (BK / 4);
            int k4 = (i % (BK / 4)) * 4;
            float4 v = *(const float4*)(A + (size_t)(row0 + m) * K + k0 + k4);
            As[k4 + 0][m] = v.x; As[k4 + 1][m] = v.y;
            As[k4 + 2][m] = v.z; As[k4 + 3][m] = v.w;
        }
        for (int i = tid; i < BK * (BN / 4); i += 256) {
            int kk = i / (BN / 4);
            int n4 = (i % (BN / 4)) * 4;
            *(float4*)&Bs[kk][n4] = *(const float4*)(Bm + (size_t)(k0 + kk) * N + col0 + n4);
        }
        __syncthreads();

        #pragma unroll
        for (int kk = 0; kk < BK; kk++) {
            float a[TM], b[TN];
            #pragma unroll
            for (int i = 0; i < TM; i += 4)
                *(float4*)&a[i] = *(const float4*)&As[kk][ty * TM + i];
            #pragma unroll
            for (int j = 0; j < TN; j += 4)
                *(float4*)&b[j] = *(const float4*)&Bs[kk][tx * TN + j];
            #pragma unroll
            for (int i = 0; i < TM; i++)
                #pragma unroll
                for (int j = 0; j < TN; j++)
                    acc[i][j] += a[i] * b[j];
        }
        __syncthreads();
    }

    #pragma unroll
    for (int i = 0; i < TM; i++) {
        const int r = row0 + ty * TM + i;
        #pragma unroll
        for (int j = 0; j < TN; j += 4) {
            float4 v;
            v.x = acc[i][j];     v.y = acc[i][j + 1];
            v.z = acc[i][j + 2]; v.w = acc[i][j + 3];
            const float* bp = bias + col0 + tx * TN + j;
            v.x += bp[0]; v.y += bp[1]; v.z += bp[2]; v.w += bp[3];
            *(float4*)(C + (size_t)r * N + col0 + tx * TN + j) = v;
        }
    }
}

// ---------------- persistent recurrent kernel (one launch = 256 steps) -------
// Grid must be exactly NBLK blocks x 256 threads (all co-resident).
// Per step: [64x1024] @ [1024x3072] split into 48 N-tiles x 3 K-slices,
// then fused gate update, with software grid barriers in between.
__launch_bounds__(256)
__global__ void gru_recurrent(const float* __restrict__ gx,    // [B*T, 3U]
                              const float* __restrict__ Ur,    // [U, 3U]
                              const float* __restrict__ brec,  // [3U]
                              float* __restrict__ h,           // [B, U] in/out
                              float* __restrict__ y)           // [B*T, U]
{
    constexpr int BK = 16;
    constexpr int KITERS = UU / BK;            // 64

    const int tid   = threadIdx.x;
    const int ntile = blockIdx.x % 48;         // N-tile (64 cols)
    const int ksl   = blockIdx.x / 48;         // K-slice (0..2)
    const int col0  = ntile * 64;
    const int it0   = (KITERS * ksl)     / 3;
    const int it1   = (KITERS * (ksl+1)) / 3;

    const int tx = tid % 16;                   // TN=4 -> 16 col groups
    const int ty = tid / 16;                   // TM=4 -> 16 row groups

    __shared__ float As[BK][64 + 4];
    __shared__ float Bs[BK][64];

    float* recp = g_rec + (size_t)ksl * BSZ * GG;
    const int gtid  = blockIdx.x * 256 + tid;

    for (int t = 0; t < TT; t++) {
        // ---- rec_partial = h[:, kslice] @ Ur[kslice, ntile] ----
        float acc[4][4];
        #pragma unroll
        for (int i = 0; i < 4; i++)
            #pragma unroll
            for (int j = 0; j < 4; j++) acc[i][j] = 0.f;

        for (int it = it0; it < it1; ++it) {
            const int k0 = it * BK;
            {   // A tile (h): 64 rows x 16 k -> 256 float4 loads, 1 per thread
                int m  = tid / 4;
                int k4 = (tid % 4) * 4;
                float4 v = *(const float4*)(h + (size_t)m * UU + k0 + k4);
                As[k4 + 0][m] = v.x; As[k4 + 1][m] = v.y;
                As[k4 + 2][m] = v.z; As[k4 + 3][m] = v.w;
            }
            {   // B tile (Ur): 16 k x 64 cols -> 256 float4 loads, 1 per thread
                int kk = tid / 16;
                int n4 = (tid % 16) * 4;
                *(float4*)&Bs[kk][n4] =
                    *(const float4*)(Ur + (size_t)(k0 + kk) * GG + col0 + n4);
            }
            __syncthreads();

            #pragma unroll
            for (int kk = 0; kk < BK; kk++) {
                float a[4], b[4];
                *(float4*)a = *(const float4*)&As[kk][ty * 4];
                *(float4*)b = *(const float4*)&Bs[kk][tx * 4];
                #pragma unroll
                for (int i = 0; i < 4; i++)
                    #pragma unroll
                    for (int j = 0; j < 4; j++)
                        acc[i][j] += a[i] * b[j];
            }
            __syncthreads();
        }

        #pragma unroll
        for (int i = 0; i < 4; i++) {
            const int r = ty * 4 + i;
            float4 v;
            v.x = acc[i][0]; v.y = acc[i][1]; v.z = acc[i][2]; v.w = acc[i][3];
            *(float4*)(recp + (size_t)r * GG + col0 + tx * 4) = v;
        }

        grid_sync();   // rec partials visible to everyone

        // ---- gate update: 65536 elems over 36864 threads ----
        for (int i = gtid; i < BSZ * UU; i += NBLK * 256) {
            const int b = i >> 10;
            const int u = i & (UU - 1);

            const float* gxr = gx + (size_t)(b * TT + t) * GG;
            const float* r0  = g_rec + (size_t)b * GG;
            const float* r1  = r0 + (size_t)BSZ * GG;
            const float* r2  = r1 + (size_t)BSZ * GG;

            const float rz = r0[u]        + r1[u]        + r2[u]        + brec[u];
            const float rr = r0[u + UU]   + r1[u + UU]   + r2[u + UU]   + brec[u + UU];
            const float rh = r0[u + 2*UU] + r1[u + 2*UU] + r2[u + 2*UU] + brec[u + 2*UU];

            const float z  = 1.f / (1.f + expf(-(gxr[u]        + rz)));
            const float r  = 1.f / (1.f + expf(-(gxr[u + UU]   + rr)));
            const float hh = tanhf(gxr[u + 2*UU] + r * rh);

            const float hp = h[i];
            const float hn = z * hp + (1.f - z) * hh;
            h[i] = hn;
            y[(size_t)(b * TT + t) * UU + u] = hn;
        }

        grid_sync();   // h fully updated before next step's GEMM
    }
}

__global__ void init_h(const float* __restrict__ s0,
                       const float* __restrict__ s1,
                       const float* __restrict__ s2)
{
    const int i = blockIdx.x * blockDim.x + threadIdx.x;
    if (i < BSZ * UU) {
        g_h[i]            = s0[i];
        g_h[BSZ*UU + i]   = s1[i];
        g_h[2*BSZ*UU + i] = s2[i];
    }
}

__global__ void write_states(float* __restrict__ out)
{
    const int i = blockIdx.x * blockDim.x + threadIdx.x;
    if (i < BSZ * UU) {
        out[i]            = g_h[i];
        out[BSZ*UU + i]   = g_h[BSZ*UU + i];
        out[2*BSZ*UU + i] = g_h[2*BSZ*UU + i];
    }
}

// ---------------- host orchestration ----------------------------------------
extern "C" void kernel_launch(void* const* d_in, const int* in_sizes, int n_in,
                              void* d_out, int out_size)
{
    const float* inputs = (const float*)d_in[0];
    const float *st[3], *W[3], *Ur[3], *bb[3];

    // Auto-detect input ordering (verified working in R0 correctness run).
    if (in_sizes[2] == BSZ * UU) {
        st[0] = (const float*)d_in[1];
        st[1] = (const float*)d_in[2];
        st[2] = (const float*)d_in[3];
        for (int l = 0; l < 3; l++) {
            W[l]  = (const float*)d_in[4 + 3*l];
            Ur[l] = (const float*)d_in[5 + 3*l];
            bb[l] = (const float*)d_in[6 + 3*l];
        }
    } else {
        for (int l = 0; l < 3; l++) {
            st[l] = (const float*)d_in[1 + 4*l];
            W[l]  = (const float*)d_in[2 + 4*l];
            Ur[l] = (const float*)d_in[3 + 4*l];
            bb[l] = (const float*)d_in[4 + 4*l];
        }
    }

    float* out = (float*)d_out;
    float *gx, *y0, *y1, *hbuf;
    cudaGetSymbolAddress((void**)&gx,   g_gx);
    cudaGetSymbolAddress((void**)&y0,   g_y0);
    cudaGetSymbolAddress((void**)&y1,   g_y1);
    cudaGetSymbolAddress((void**)&hbuf, g_h);

    init_h<<<(BSZ*UU + 255)/256, 256>>>(st[0], st[1], st[2]);

    const int    KIN[3]  = {FF, UU, UU};
    const float* xin[3]  = {inputs, y0, y1};
    float*       yout[3] = {y0, y1, out};

    for (int l = 0; l < 3; l++) {
        dim3 gi(GG / 128, MIN_ / 128, 1);
        gemm_bias<128,128,16,8,8><<<gi, 256>>>(xin[l], W[l], bb[l], gx,
                                               MIN_, GG, KIN[l]);
        gru_recurrent<<<NBLK, 256>>>(gx, Ur[l], bb[l] + GG,
                                     hbuf + l * BSZ * UU, yout[l]);
    }

    write_states<<<(BSZ*UU + 255)/256, 256>>>(out + (size_t)MIN_ * UU);
}

// round 4
// speedup vs baseline: 1.1190x; 1.1190x over previous
#include <cuda_runtime.h>
#include <cuda_bf16.h>
#include <math.h>
#include <stdint.h>

#define BSZ 64
#define TT  256
#define FF  256
#define UU  1024
#define GG  3072          // 3*U
#define MIN_ (BSZ*TT)     // 16384 rows for the input projection GEMM

#define NBLK 144          // persistent grid for recurrent part

// ---------------- scratch (static device memory; no allocations) -------------
__device__ float g_gx[(size_t)MIN_ * GG];     // per-layer input projections
__device__ float g_y0[(size_t)MIN_ * UU];     // layer0 output
__device__ float g_y1[(size_t)MIN_ * UU];     // layer1 output
__device__ float g_rec[3 * BSZ * GG];         // split-K partials of h @ Ur
__device__ float g_h[3 * BSZ * UU];           // running hidden states

// bf16 hi/lo split buffers for tensor-core input projections
__device__ __align__(16) __nv_bfloat16 g_xhi[(size_t)MIN_ * UU];
__device__ __align__(16) __nv_bfloat16 g_xlo[(size_t)MIN_ * UU];
__device__ __align__(16) __nv_bfloat16 g_wthi[(size_t)GG * UU];   // W^T [3072 x K]
__device__ __align__(16) __nv_bfloat16 g_wtlo[(size_t)GG * UU];

__device__ unsigned g_bar_count = 0;
__device__ unsigned g_bar_phase = 0;

// ================= warp-MMA helpers (family-portable, sm_80+) =================
__device__ __forceinline__ uint32_t smem_to_u32(const void* p) {
    uint32_t a;
    asm("{ .reg .u64 t; cvta.to.shared.u64 t, %1; cvt.u32.u64 %0, t; }"
        : "=r"(a) : "l"(p));
    return a;
}
#define SW128(x) ((x) ^ (((x) >> 3) & 0x70))

__device__ __forceinline__ void ldsm_x4(uint32_t (&r)[4], uint32_t addr) {
    asm volatile("ldmatrix.sync.aligned.m8n8.x4.shared.b16 {%0,%1,%2,%3}, [%4];"
                 : "=r"(r[0]), "=r"(r[1]), "=r"(r[2]), "=r"(r[3]) : "r"(addr));
}
__device__ __forceinline__ void mma_bf16(float (&c)[4], const uint32_t (&a)[4],
                                         uint32_t b0, uint32_t b1) {
    asm volatile(
        "mma.sync.aligned.m16n8k16.row.col.f32.bf16.bf16.f32 "
        "{%0,%1,%2,%3}, {%4,%5,%6,%7}, {%8,%9}, {%0,%1,%2,%3};"
        : "+f"(c[0]), "+f"(c[1]), "+f"(c[2]), "+f"(c[3])
        : "r"(a[0]), "r"(a[1]), "r"(a[2]), "r"(a[3]), "r"(b0), "r"(b1));
}
__device__ __forceinline__ void cp_async16(uint32_t saddr, const void* g) {
    asm volatile("cp.async.cg.shared.global [%0], [%1], 16;"
                 :: "r"(saddr), "l"(g));
}
#define CP_COMMIT() asm volatile("cp.async.commit_group;" ::: "memory")
#define CP_WAIT(n)  asm volatile("cp.async.wait_group %0;" :: "n"(n) : "memory")

// ================= tensor-core input projection GEMM =========================
// C[16384,3072] = X @ W + bias via 3-term bf16 split on mma.sync.
// CTA tile 128x128, 8 warps (2x4), warp tile 64x32, K-chunks of 64, dbl-buffered.
#define KC 64
#define OFF_AHI 0
#define OFF_ALO (16*1024)
#define OFF_BHI (32*1024)
#define OFF_BLO (48*1024)
#define BUF_SZ  (64*1024)
#define GEMM_SMEM (2*BUF_SZ)

__launch_bounds__(256, 1)
__global__ void gemm_tc(const __nv_bfloat16* __restrict__ Ahi,
                        const __nv_bfloat16* __restrict__ Alo,
                        const __nv_bfloat16* __restrict__ Bhi,  // W^T [3072 x K]
                        const __nv_bfloat16* __restrict__ Blo,
                        const float* __restrict__ bias,
                        float* __restrict__ C,
                        int K)
{
    extern __shared__ char sm[];
    const uint32_t smb = smem_to_u32(sm);
    const int tid  = threadIdx.x;
    const int wid  = tid >> 5;
    const int lane = tid & 31;
    const int wm   = wid >> 2;          // 0..1 : M
    const int wn   = wid & 3;           // 0..3 : N
    const int row0 = blockIdx.y * 128;
    const int col0 = blockIdx.x * 128;

    float acc[4][4][4];
    #pragma unroll
    for (int mt = 0; mt < 4; mt++)
        #pragma unroll
        for (int nt = 0; nt < 4; nt++)
            #pragma unroll
            for (int j = 0; j < 4; j++) acc[mt][nt][j] = 0.f;

    const int ns = K / KC;

    // ---- async fill of one K-chunk into buffer b ----
    auto load_chunk = [&](int s) {
        const int b = s & 1;
        const uint32_t bufb = smb + b * BUF_SZ;
        const int k0 = s * KC;
        #pragma unroll 2
        for (int i = tid; i < 1024; i += 256) {          // A: 128 rows x 8 chunks
            int r = i >> 3, j = i & 7;
            size_t go = (size_t)(row0 + r) * K + k0 + j * 8;
            uint32_t so = SW128(r * 128 + j * 16);
            cp_async16(bufb + OFF_AHI + so, Ahi + go);
            cp_async16(bufb + OFF_ALO + so, Alo + go);
        }
        #pragma unroll 2
        for (int i = tid; i < 1024; i += 256) {          // B: 128 n-rows x 8 chunks
            int n = i >> 3, j = i & 7;
            size_t go = (size_t)(col0 + n) * K + k0 + j * 8;
            uint32_t so = SW128(n * 128 + j * 16);
            cp_async16(bufb + OFF_BHI + so, Bhi + go);
            cp_async16(bufb + OFF_BLO + so, Blo + go);
        }
        CP_COMMIT();
    };

    load_chunk(0);

    for (int s = 0; s < ns; s++) {
        if (s + 1 < ns) { load_chunk(s + 1); CP_WAIT(1); }
        else            { CP_WAIT(0); }
        __syncthreads();

        const uint32_t bufb = smb + (s & 1) * BUF_SZ;

        #pragma unroll
        for (int k16 = 0; k16 < 4; k16++) {
            const int kc = k16 * 16 + ((lane >> 4) << 3);   // lane's k-col for ldsm
            // A fragments (hi & lo) for 4 m-tiles
            uint32_t ahi[4][4], alo[4][4];
            #pragma unroll
            for (int mt = 0; mt < 4; mt++) {
                const int r = wm * 64 + mt * 16 + (lane & 15);
                const uint32_t so = SW128(r * 128 + kc * 2);
                ldsm_x4(ahi[mt], bufb + OFF_AHI + so);
                ldsm_x4(alo[mt], bufb + OFF_ALO + so);
            }
            // B fragments: 2 groups of 16 n-rows cover 4 n-tiles
            #pragma unroll
            for (int bg = 0; bg < 2; bg++) {
                const int n = wn * 32 + bg * 16 + ((lane & 16) >> 1) + (lane & 7);
                const int kcb = k16 * 16 + ((lane & 8) ? 8 : 0);
                const uint32_t so = SW128(n * 128 + kcb * 2);
                uint32_t bhi[4], blo[4];
                ldsm_x4(bhi, bufb + OFF_BHI + so);
                ldsm_x4(blo, bufb + OFF_BLO + so);
                #pragma unroll
                for (int mt = 0; mt < 4; mt++) {
                    mma_bf16(acc[mt][bg*2+0], ahi[mt], bhi[0], bhi[1]);
                    mma_bf16(acc[mt][bg*2+0], ahi[mt], blo[0], blo[1]);
                    mma_bf16(acc[mt][bg*2+0], alo[mt], bhi[0], bhi[1]);
                    mma_bf16(acc[mt][bg*2+1], ahi[mt], bhi[2], bhi[3]);
                    mma_bf16(acc[mt][bg*2+1], ahi[mt], blo[2], blo[3]);
                    mma_bf16(acc[mt][bg*2+1], alo[mt], bhi[2], bhi[3]);
                }
            }
        }
        __syncthreads();
    }

    // ---- epilogue: add bias, write fp32 C ----
    #pragma unroll
    for (int mt = 0; mt < 4; mt++) {
        const int row = row0 + wm * 64 + mt * 16 + (lane >> 2);
        #pragma unroll
        for (int nt = 0; nt < 4; nt++) {
            const int col = col0 + wn * 32 + nt * 8 + 2 * (lane & 3);
            const float2 bv = *(const float2*)(bias + col);
            float2 v0, v1;
            v0.x = acc[mt][nt][0] + bv.x;  v0.y = acc[mt][nt][1] + bv.y;
            v1.x = acc[mt][nt][2] + bv.x;  v1.y = acc[mt][nt][3] + bv.y;
            *(float2*)(C + (size_t)row * GG + col)       = v0;
            *(float2*)(C + (size_t)(row + 8) * GG + col) = v1;
        }
    }
}

// ================= conversion kernels =========================================
__global__ void split_x(const float* __restrict__ x,
                        __nv_bfloat16* __restrict__ hi,
                        __nv_bfloat16* __restrict__ lo, int n)
{
    int i = blockIdx.x * 256 + threadIdx.x;
    if (i < n) {
        float v = x[i];
        __nv_bfloat16 h = __float2bfloat16(v);
        hi[i] = h;
        lo[i] = __float2bfloat16(v - __bfloat162float(h));
    }
}

__global__ void transpose_split(const float* __restrict__ W,   // [K x 3072]
                                __nv_bfloat16* __restrict__ Th, // [3072 x K]
                                __nv_bfloat16* __restrict__ Tl,
                                int K)
{
    __shared__ float tile[32][33];
    const int nt = blockIdx.x * 32;
    const int kt = blockIdx.y * 32;
    const int tx = threadIdx.x, ty = threadIdx.y;   // (32, 8)
    #pragma unroll
    for (int r = 0; r < 32; r += 8)
        tile[ty + r][tx] = W[(size_t)(kt + ty + r) * GG + nt + tx];
    __syncthreads();
    #pragma unroll
    for (int r = 0; r < 32; r += 8) {
        float v = tile[tx][ty + r];
        __nv_bfloat16 h = __float2bfloat16(v);
        size_t o = (size_t)(nt + ty + r) * K + kt + tx;
        Th[o] = h;
        Tl[o] = __float2bfloat16(v - __bfloat162float(h));
    }
}

// ================= software grid barrier ======================================
__device__ __forceinline__ void grid_sync()
{
    __syncthreads();
    if (threadIdx.x == 0) {
        __threadfence();
        unsigned gen = atomicAdd(&g_bar_phase, 0u);
        unsigned arrived = atomicAdd(&g_bar_count, 1u);
        if (arrived == NBLK - 1) {
            g_bar_count = 0;
            __threadfence();
            atomicExch(&g_bar_phase, gen + 1u);
        } else {
            while (atomicAdd(&g_bar_phase, 0u) == gen) { __nanosleep(32); }
        }
        __threadfence();
    }
    __syncthreads();
}

// ================= persistent recurrent kernel (fp32) =========================
__launch_bounds__(256)
__global__ void gru_recurrent(const float* __restrict__ gx,
                              const float* __restrict__ Ur,
                              const float* __restrict__ brec,
                              float* __restrict__ h,
                              float* __restrict__ y)
{
    constexpr int BK = 16;
    constexpr int KITERS = UU / BK;

    const int tid   = threadIdx.x;
    const int ntile = blockIdx.x % 48;
    const int ksl   = blockIdx.x / 48;
    const int col0  = ntile * 64;
    const int it0   = (KITERS * ksl)     / 3;
    const int it1   = (KITERS * (ksl+1)) / 3;

    const int tx = tid % 16;
    const int ty = tid / 16;

    __shared__ float As[BK][64 + 4];
    __shared__ float Bs[BK][64];

    float* recp = g_rec + (size_t)ksl * BSZ * GG;
    const int gtid = blockIdx.x * 256 + tid;

    for (int t = 0; t < TT; t++) {
        float acc[4][4];
        #pragma unroll
        for (int i = 0; i < 4; i++)
            #pragma unroll
            for (int j = 0; j < 4; j++) acc[i][j] = 0.f;

        for (int it = it0; it < it1; ++it) {
            const int k0 = it * BK;
            {
                int m  = tid / 4;
                int k4 = (tid % 4) * 4;
                float4 v = *(const float4*)(h + (size_t)m * UU + k0 + k4);
                As[k4 + 0][m] = v.x; As[k4 + 1][m] = v.y;
                As[k4 + 2][m] = v.z; As[k4 + 3][m] = v.w;
            }
            {
                int kk = tid / 16;
                int n4 = (tid % 16) * 4;
                *(float4*)&Bs[kk][n4] =
                    *(const float4*)(Ur + (size_t)(k0 + kk) * GG + col0 + n4);
            }
            __syncthreads();

            #pragma unroll
            for (int kk = 0; kk < BK; kk++) {
                float a[4], b[4];
                *(float4*)a = *(const float4*)&As[kk][ty * 4];
                *(float4*)b = *(const float4*)&Bs[kk][tx * 4];
                #pragma unroll
                for (int i = 0; i < 4; i++)
                    #pragma unroll
                    for (int j = 0; j < 4; j++)
                        acc[i][j] += a[i] * b[j];
            }
            __syncthreads();
        }

        #pragma unroll
        for (int i = 0; i < 4; i++) {
            const int r = ty * 4 + i;
            float4 v;
            v.x = acc[i][0]; v.y = acc[i][1]; v.z = acc[i][2]; v.w = acc[i][3];
            *(float4*)(recp + (size_t)r * GG + col0 + tx * 4) = v;
        }

        grid_sync();

        for (int i = gtid; i < BSZ * UU; i += NBLK * 256) {
            const int b = i >> 10;
            const int u = i & (UU - 1);

            const float* gxr = gx + (size_t)(b * TT + t) * GG;
            const float* r0  = g_rec + (size_t)b * GG;
            const float* r1  = r0 + (size_t)BSZ * GG;
            const float* r2  = r1 + (size_t)BSZ * GG;

            const float rz = r0[u]        + r1[u]        + r2[u]        + brec[u];
            const float rr = r0[u + UU]   + r1[u + UU]   + r2[u + UU]   + brec[u + UU];
            const float rh = r0[u + 2*UU] + r1[u + 2*UU] + r2[u + 2*UU] + brec[u + 2*UU];

            const float z  = 1.f / (1.f + expf(-(gxr[u]        + rz)));
            const float r  = 1.f / (1.f + expf(-(gxr[u + UU]   + rr)));
            const float hh = tanhf(gxr[u + 2*UU] + r * rh);

            const float hp = h[i];
            const float hn = z * hp + (1.f - z) * hh;
            h[i] = hn;
            y[(size_t)(b * TT + t) * UU + u] = hn;
        }

        grid_sync();
    }
}

__global__ void init_h(const float* __restrict__ s0,
                       const float* __restrict__ s1,
                       const float* __restrict__ s2)
{
    const int i = blockIdx.x * blockDim.x + threadIdx.x;
    if (i < BSZ * UU) {
        g_h[i]            = s0[i];
        g_h[BSZ*UU + i]   = s1[i];
        g_h[2*BSZ*UU + i] = s2[i];
    }
}

__global__ void write_states(float* __restrict__ out)
{
    const int i = blockIdx.x * blockDim.x + threadIdx.x;
    if (i < BSZ * UU) {
        out[i]            = g_h[i];
        out[BSZ*UU + i]   = g_h[BSZ*UU + i];
        out[2*BSZ*UU + i] = g_h[2*BSZ*UU + i];
    }
}

// ================= host orchestration ========================================
extern "C" void kernel_launch(void* const* d_in, const int* in_sizes, int n_in,
                              void* d_out, int out_size)
{
    const float* inputs = (const float*)d_in[0];
    const float *st[3], *W[3], *Ur[3], *bb[3];

    if (in_sizes[2] == BSZ * UU) {
        st[0] = (const float*)d_in[1];
        st[1] = (const float*)d_in[2];
        st[2] = (const float*)d_in[3];
        for (int l = 0; l < 3; l++) {
            W[l]  = (const float*)d_in[4 + 3*l];
            Ur[l] = (const float*)d_in[5 + 3*l];
            bb[l] = (const float*)d_in[6 + 3*l];
        }
    } else {
        for (int l = 0; l < 3; l++) {
            st[l] = (const float*)d_in[1 + 4*l];
            W[l]  = (const float*)d_in[2 + 4*l];
            Ur[l] = (const float*)d_in[3 + 4*l];
            bb[l] = (const float*)d_in[4 + 4*l];
        }
    }

    float* out = (float*)d_out;
    float *gx, *y0, *y1, *hbuf;
    __nv_bfloat16 *xhi, *xlo, *wthi, *wtlo;
    cudaGetSymbolAddress((void**)&gx,   g_gx);
    cudaGetSymbolAddress((void**)&y0,   g_y0);
    cudaGetSymbolAddress((void**)&y1,   g_y1);
    cudaGetSymbolAddress((void**)&hbuf, g_h);
    cudaGetSymbolAddress((void**)&xhi,  g_xhi);
    cudaGetSymbolAddress((void**)&xlo,  g_xlo);
    cudaGetSymbolAddress((void**)&wthi, g_wthi);
    cudaGetSymbolAddress((void**)&wtlo, g_wtlo);

    cudaFuncSetAttribute(gemm_tc, cudaFuncAttributeMaxDynamicSharedMemorySize,
                         GEMM_SMEM);

    init_h<<<(BSZ*UU + 255)/256, 256>>>(st[0], st[1], st[2]);

    const int    KIN[3]  = {FF, UU, UU};
    const float* xin[3]  = {inputs, y0, y1};
    float*       yout[3] = {y0, y1, out};

    for (int l = 0; l < 3; l++) {
        const int K = KIN[l];
        split_x<<<(MIN_ * K + 255)/256, 256>>>(xin[l], xhi, xlo, MIN_ * K);
        transpose_split<<<dim3(GG/32, K/32), dim3(32, 8)>>>(W[l], wthi, wtlo, K);
        gemm_tc<<<dim3(GG/128, MIN_/128), 256, GEMM_SMEM>>>(xhi, xlo, wthi, wtlo,
                                                            bb[l], gx, K);
        gru_recurrent<<<NBLK, 256>>>(gx, Ur[l], bb[l] + GG,
                                     hbuf + l * BSZ * UU, yout[l]);
    }

    write_states<<<(BSZ*UU + 255)/256, 256>>>(out + (size_t)MIN_ * UU);
}

// round 5
// speedup vs baseline: 2.9643x; 2.6490x over previous
#include <cuda_runtime.h>
#include <cuda_bf16.h>
#include <math.h>
#include <stdint.h>

#define BSZ 64
#define TT  256
#define FF  256
#define UU  1024
#define GG  3072
#define MIN_ (BSZ*TT)

#define RBLK 128          // persistent blocks (1 per SM, 128 <= 148)

// ---------------- scratch (static device memory) -----------------------------
__device__ float g_gx[(size_t)MIN_ * GG];
__device__ float g_y0[(size_t)MIN_ * UU];
__device__ float g_y1[(size_t)MIN_ * UU];

__device__ __align__(16) __nv_bfloat16 g_xhi[(size_t)MIN_ * UU];
__device__ __align__(16) __nv_bfloat16 g_xlo[(size_t)MIN_ * UU];
__device__ __align__(16) __nv_bfloat16 g_wthi[(size_t)GG * UU];   // W^T
__device__ __align__(16) __nv_bfloat16 g_wtlo[(size_t)GG * UU];
__device__ __align__(16) __nv_bfloat16 g_urthi[(size_t)GG * UU];  // Ur^T
__device__ __align__(16) __nv_bfloat16 g_urtlo[(size_t)GG * UU];
__device__ __align__(16) __nv_bfloat16 g_hhi[2 * BSZ * UU];       // ping-pong h
__device__ __align__(16) __nv_bfloat16 g_hlo[2 * BSZ * UU];

__device__ unsigned g_bar_count = 0;
__device__ unsigned g_bar_phase = 0;

// ================= warp-MMA helpers ==========================================
__device__ __forceinline__ uint32_t smem_to_u32(const void* p) {
    uint32_t a;
    asm("{ .reg .u64 t; cvta.to.shared.u64 t, %1; cvt.u32.u64 %0, t; }"
        : "=r"(a) : "l"(p));
    return a;
}
#define SW128(x) ((x) ^ (((x) >> 3) & 0x70))

__device__ __forceinline__ void ldsm_x4(uint32_t (&r)[4], uint32_t addr) {
    asm volatile("ldmatrix.sync.aligned.m8n8.x4.shared.b16 {%0,%1,%2,%3}, [%4];"
                 : "=r"(r[0]), "=r"(r[1]), "=r"(r[2]), "=r"(r[3]) : "r"(addr));
}
__device__ __forceinline__ void mma_bf16(float (&c)[4], const uint32_t (&a)[4],
                                         uint32_t b0, uint32_t b1) {
    asm volatile(
        "mma.sync.aligned.m16n8k16.row.col.f32.bf16.bf16.f32 "
        "{%0,%1,%2,%3}, {%4,%5,%6,%7}, {%8,%9}, {%0,%1,%2,%3};"
        : "+f"(c[0]), "+f"(c[1]), "+f"(c[2]), "+f"(c[3])
        : "r"(a[0]), "r"(a[1]), "r"(a[2]), "r"(a[3]), "r"(b0), "r"(b1));
}
__device__ __forceinline__ void cp_async16(uint32_t saddr, const void* g) {
    asm volatile("cp.async.cg.shared.global [%0], [%1], 16;"
                 :: "r"(saddr), "l"(g));
}
#define CP_COMMIT() asm volatile("cp.async.commit_group;" ::: "memory")
#define CP_WAIT(n)  asm volatile("cp.async.wait_group %0;" :: "n"(n) : "memory")

// ================= input projection GEMM (proven in R4) ======================
#define KC 64
#define OFF_AHI 0
#define OFF_ALO (16*1024)
#define OFF_BHI (32*1024)
#define OFF_BLO (48*1024)
#define BUF_SZ  (64*1024)
#define GEMM_SMEM (2*BUF_SZ)

__launch_bounds__(256, 1)
__global__ void gemm_tc(const __nv_bfloat16* __restrict__ Ahi,
                        const __nv_bfloat16* __restrict__ Alo,
                        const __nv_bfloat16* __restrict__ Bhi,
                        const __nv_bfloat16* __restrict__ Blo,
                        const float* __restrict__ bias,
                        float* __restrict__ C,
                        int K)
{
    extern __shared__ char sm[];
    const uint32_t smb = smem_to_u32(sm);
    const int tid  = threadIdx.x;
    const int wid  = tid >> 5;
    const int lane = tid & 31;
    const int wm   = wid >> 2;
    const int wn   = wid & 3;
    const int row0 = blockIdx.y * 128;
    const int col0 = blockIdx.x * 128;

    float acc[4][4][4];
    #pragma unroll
    for (int mt = 0; mt < 4; mt++)
        #pragma unroll
        for (int nt = 0; nt < 4; nt++)
            #pragma unroll
            for (int j = 0; j < 4; j++) acc[mt][nt][j] = 0.f;

    const int ns = K / KC;

    auto load_chunk = [&](int s) {
        const int b = s & 1;
        const uint32_t bufb = smb + b * BUF_SZ;
        const int k0 = s * KC;
        #pragma unroll 2
        for (int i = tid; i < 1024; i += 256) {
            int r = i >> 3, j = i & 7;
            size_t go = (size_t)(row0 + r) * K + k0 + j * 8;
            uint32_t so = SW128(r * 128 + j * 16);
            cp_async16(bufb + OFF_AHI + so, Ahi + go);
            cp_async16(bufb + OFF_ALO + so, Alo + go);
        }
        #pragma unroll 2
        for (int i = tid; i < 1024; i += 256) {
            int n = i >> 3, j = i & 7;
            size_t go = (size_t)(col0 + n) * K + k0 + j * 8;
            uint32_t so = SW128(n * 128 + j * 16);
            cp_async16(bufb + OFF_BHI + so, Bhi + go);
            cp_async16(bufb + OFF_BLO + so, Blo + go);
        }
        CP_COMMIT();
    };

    load_chunk(0);

    for (int s = 0; s < ns; s++) {
        if (s + 1 < ns) { load_chunk(s + 1); CP_WAIT(1); }
        else            { CP_WAIT(0); }
        __syncthreads();

        const uint32_t bufb = smb + (s & 1) * BUF_SZ;

        #pragma unroll
        for (int k16 = 0; k16 < 4; k16++) {
            const int kc = k16 * 16 + ((lane >> 4) << 3);
            uint32_t ahi[4][4], alo[4][4];
            #pragma unroll
            for (int mt = 0; mt < 4; mt++) {
                const int r = wm * 64 + mt * 16 + (lane & 15);
                const uint32_t so = SW128(r * 128 + kc * 2);
                ldsm_x4(ahi[mt], bufb + OFF_AHI + so);
                ldsm_x4(alo[mt], bufb + OFF_ALO + so);
            }
            #pragma unroll
            for (int bg = 0; bg < 2; bg++) {
                const int n = wn * 32 + bg * 16 + ((lane & 16) >> 1) + (lane & 7);
                const int kcb = k16 * 16 + ((lane & 8) ? 8 : 0);
                const uint32_t so = SW128(n * 128 + kcb * 2);
                uint32_t bhi[4], blo[4];
                ldsm_x4(bhi, bufb + OFF_BHI + so);
                ldsm_x4(blo, bufb + OFF_BLO + so);
                #pragma unroll
                for (int mt = 0; mt < 4; mt++) {
                    mma_bf16(acc[mt][bg*2+0], ahi[mt], bhi[0], bhi[1]);
                    mma_bf16(acc[mt][bg*2+0], ahi[mt], blo[0], blo[1]);
                    mma_bf16(acc[mt][bg*2+0], alo[mt], bhi[0], bhi[1]);
                    mma_bf16(acc[mt][bg*2+1], ahi[mt], bhi[2], bhi[3]);
                    mma_bf16(acc[mt][bg*2+1], ahi[mt], blo[2], blo[3]);
                    mma_bf16(acc[mt][bg*2+1], alo[mt], bhi[2], bhi[3]);
                }
            }
        }
        __syncthreads();
    }

    #pragma unroll
    for (int mt = 0; mt < 4; mt++) {
        const int row = row0 + wm * 64 + mt * 16 + (lane >> 2);
        #pragma unroll
        for (int nt = 0; nt < 4; nt++) {
            const int col = col0 + wn * 32 + nt * 8 + 2 * (lane & 3);
            const float2 bv = *(const float2*)(bias + col);
            float2 v0, v1;
            v0.x = acc[mt][nt][0] + bv.x;  v0.y = acc[mt][nt][1] + bv.y;
            v1.x = acc[mt][nt][2] + bv.x;  v1.y = acc[mt][nt][3] + bv.y;
            *(float2*)(C + (size_t)row * GG + col)       = v0;
            *(float2*)(C + (size_t)(row + 8) * GG + col) = v1;
        }
    }
}

// ================= conversion kernels =========================================
__global__ void split_x(const float* __restrict__ x,
                        __nv_bfloat16* __restrict__ hi,
                        __nv_bfloat16* __restrict__ lo, int n)
{
    int i = blockIdx.x * 256 + threadIdx.x;
    if (i < n) {
        float v = x[i];
        __nv_bfloat16 h = __float2bfloat16(v);
        hi[i] = h;
        lo[i] = __float2bfloat16(v - __bfloat162float(h));
    }
}

__global__ void transpose_split(const float* __restrict__ W,   // [K x 3072]
                                __nv_bfloat16* __restrict__ Th, // [3072 x K]
                                __nv_bfloat16* __restrict__ Tl,
                                int K)
{
    __shared__ float tile[32][33];
    const int nt = blockIdx.x * 32;
    const int kt = blockIdx.y * 32;
    const int tx = threadIdx.x, ty = threadIdx.y;
    #pragma unroll
    for (int r = 0; r < 32; r += 8)
        tile[ty + r][tx] = W[(size_t)(kt + ty + r) * GG + nt + tx];
    __syncthreads();
    #pragma unroll
    for (int r = 0; r < 32; r += 8) {
        float v = tile[tx][ty + r];
        __nv_bfloat16 h = __float2bfloat16(v);
        size_t o = (size_t)(nt + ty + r) * K + kt + tx;
        Th[o] = h;
        Tl[o] = __float2bfloat16(v - __bfloat162float(h));
    }
}

__global__ void split_state(const float* __restrict__ st)
{
    int i = blockIdx.x * 256 + threadIdx.x;
    if (i < BSZ * UU) {
        float v = st[i];
        __nv_bfloat16 h = __float2bfloat16(v);
        g_hhi[i] = h;
        g_hlo[i] = __float2bfloat16(v - __bfloat162float(h));
    }
}

// ================= software grid barrier ======================================
__device__ __forceinline__ void grid_sync()
{
    __syncthreads();
    if (threadIdx.x == 0) {
        __threadfence();
        unsigned gen = atomicAdd(&g_bar_phase, 0u);
        unsigned arrived = atomicAdd(&g_bar_count, 1u);
        if (arrived == RBLK - 1) {
            g_bar_count = 0;
            __threadfence();
            atomicExch(&g_bar_phase, gen + 1u);
        } else {
            while (atomicAdd(&g_bar_phase, 0u) == gen) { __nanosleep(32); }
        }
        __threadfence();
    }
    __syncthreads();
}

// ================= persistent tensor-core recurrent kernel ===================
// 128 blocks x 128 threads. Block = (mhalf: 32 batch rows) x (utile: 16 u-cols).
// Computes z/r/hh columns for its own slice -> gate update fully local.
// Ur^T slice (48 rows x 1024 k, hi+lo = 192KB) cached in SMEM for all 256 steps.
#define SM_B 0
#define SM_A 196608
#define REC_SMEM 229376   // 192KB B + 2 x 16KB A double-buffer

__launch_bounds__(128, 1)
__global__ void gru_recurrent(const float* __restrict__ gx,
                              const float* __restrict__ brec,
                              const float* __restrict__ st,
                              float* __restrict__ y,
                              float* __restrict__ stOut)
{
    extern __shared__ char sm[];
    const uint32_t smb = smem_to_u32(sm);
    const int tid  = threadIdx.x;
    const int lane = tid & 31;
    const int w    = tid >> 5;
    const int wm   = w >> 1;                 // 0..1 (16-row half)
    const int wn   = w & 1;                  // 0..1 (8-u half)
    const int mhalf = blockIdx.x & 1;
    const int utile = blockIdx.x >> 1;       // 0..63
    const int row0  = mhalf * 32;
    const int u0    = utile * 16;

    // ---- fill B SMEM once: 48 rows (wn-group x gate x 8) x 1024 k, hi+lo ----
    for (int g = tid; g < 12288; g += 128) {
        int term = g / 6144, idx = g % 6144;
        int n = idx >> 7, g16 = idx & 127;
        int wng = n / 24, rem = n % 24, gate = rem >> 3, i = rem & 7;
        int urow = gate * 1024 + u0 + wng * 8 + i;
        const __nv_bfloat16* src =
            (term ? g_urtlo : g_urthi) + (size_t)urow * UU + g16 * 8;
        uint32_t so = SM_B + (uint32_t)term * 98304u + (uint32_t)n * 2048u +
                      (((uint32_t)g16 * 16u) ^ (((uint32_t)(n & 7)) << 4));
        cp_async16(smb + so, src);
    }
    CP_COMMIT();

    // ---- per-thread constants ----
    const int brow = row0 + wm * 16 + (lane >> 2);      // rows brow, brow+8
    const int uc   = u0 + wn * 8 + 2 * (lane & 3);      // cols uc, uc+1

    float bz[2], br_[2], bh_[2];
    { float2 v = *(const float2*)(brec + uc);        bz[0]=v.x; bz[1]=v.y; }
    { float2 v = *(const float2*)(brec + 1024 + uc); br_[0]=v.x; br_[1]=v.y; }
    { float2 v = *(const float2*)(brec + 2048 + uc); bh_[0]=v.x; bh_[1]=v.y; }

    float hp[2][2];
    { float2 v = *(const float2*)(st + (size_t)brow * UU + uc);
      hp[0][0]=v.x; hp[0][1]=v.y; }
    { float2 v = *(const float2*)(st + (size_t)(brow+8) * UU + uc);
      hp[1][0]=v.x; hp[1][1]=v.y; }

    const float* gxp[2];
    gxp[0] = gx + (size_t)brow * TT * GG;
    gxp[1] = gx + (size_t)(brow + 8) * TT * GG;
    float* yp[2];
    yp[0] = y + (size_t)brow * TT * UU + uc;
    yp[1] = y + (size_t)(brow + 8) * TT * UU + uc;

    // ---- A chunk prefetch (KC=128): 32 rows x 128 k, hi+lo, per buffer ----
    auto fillA = [&](int ck, const __nv_bfloat16* hhi, const __nv_bfloat16* hlo) {
        const int k0 = ck * 128;
        #pragma unroll
        for (int j = 0; j < 8; j++) {
            int g = tid + j * 128;
            int term = g >> 9, idx = g & 511, r = idx >> 4, g16 = idx & 15;
            const __nv_bfloat16* src =
                (term ? hlo : hhi) + (size_t)(row0 + r) * UU + k0 + g16 * 8;
            uint32_t so = SM_A + (uint32_t)(ck & 1) * 16384u +
                          (uint32_t)term * 8192u + (uint32_t)r * 256u +
                          (((uint32_t)g16 * 16u) ^ (((uint32_t)(r & 7)) << 4));
            cp_async16(smb + so, src);
        }
        CP_COMMIT();
    };

    for (int t = 0; t < TT; t++) {
        const __nv_bfloat16* hhi = g_hhi + (t & 1) * (BSZ * UU);
        const __nv_bfloat16* hlo = g_hlo + (t & 1) * (BSZ * UU);
        __nv_bfloat16* nhhi = g_hhi + ((t + 1) & 1) * (BSZ * UU);
        __nv_bfloat16* nhlo = g_hlo + ((t + 1) & 1) * (BSZ * UU);

        fillA(0, hhi, hlo);
        fillA(1, hhi, hlo);

        // prefetch this step's gx operands (hide DRAM latency under GEMM)
        float gz[2][2], gr[2][2], gh[2][2];
        #pragma unroll
        for (int rr = 0; rr < 2; rr++) {
            const float* gq = gxp[rr];
            float2 v;
            v = *(const float2*)(gq + uc);        gz[rr][0]=v.x; gz[rr][1]=v.y;
            v = *(const float2*)(gq + 1024 + uc); gr[rr][0]=v.x; gr[rr][1]=v.y;
            v = *(const float2*)(gq + 2048 + uc); gh[rr][0]=v.x; gh[rr][1]=v.y;
        }

        float acc[3][4], acc2[3][4];
        #pragma unroll
        for (int g = 0; g < 3; g++)
            #pragma unroll
            for (int j = 0; j < 4; j++) { acc[g][j] = 0.f; acc2[g][j] = 0.f; }

        #pragma unroll 1
        for (int ck = 0; ck < 8; ck++) {
            if (ck < 7) { CP_WAIT(1); } else { CP_WAIT(0); }
            __syncthreads();

            const uint32_t Ab = smb + SM_A + (uint32_t)(ck & 1) * 16384u;
            const uint32_t kbase = (uint32_t)ck * 256u;

            #pragma unroll
            for (int k32 = 0; k32 < 4; k32++) {
                uint32_t bh4[3][4], bl4[3][4];
                #pragma unroll
                for (int g = 0; g < 3; g++) {
                    uint32_t n = (uint32_t)(wn * 24 + g * 8 + (lane & 7));
                    uint32_t kb = kbase + (uint32_t)k32 * 64u +
                                  (uint32_t)((lane >> 3) & 3) * 16u;
                    uint32_t so = SM_B + n * 2048u + (kb ^ ((n & 7u) << 4));
                    ldsm_x4(bh4[g], smb + so);
                    ldsm_x4(bl4[g], smb + so + 98304u);
                }
                #pragma unroll
                for (int hf = 0; hf < 2; hf++) {
                    uint32_t ah[4], al[4];
                    uint32_t r = (uint32_t)(wm * 16 + (lane & 15));
                    uint32_t kb = (uint32_t)(k32 * 2 + hf) * 32u +
                                  (uint32_t)(lane >> 4) * 16u;
                    uint32_t so = Ab + r * 256u + (kb ^ ((r & 7u) << 4));
                    ldsm_x4(ah, so);
                    ldsm_x4(al, so + 8192u);
                    #pragma unroll
                    for (int g = 0; g < 3; g++) {
                        mma_bf16(acc[g],  ah, bh4[g][hf*2], bh4[g][hf*2+1]);
                        mma_bf16(acc2[g], ah, bl4[g][hf*2], bl4[g][hf*2+1]);
                        mma_bf16(acc2[g], al, bh4[g][hf*2], bh4[g][hf*2+1]);
                    }
                }
            }
            __syncthreads();
            if (ck + 2 < 8) fillA(ck + 2, hhi, hlo);
        }

        // ---- fused gate update (register-local) ----
        #pragma unroll
        for (int g = 0; g < 3; g++)
            #pragma unroll
            for (int j = 0; j < 4; j++) acc[g][j] += acc2[g][j];

        #pragma unroll
        for (int rr = 0; rr < 2; rr++) {
            float hn[2];
            #pragma unroll
            for (int c = 0; c < 2; c++) {
                const int j = rr * 2 + c;
                const float zz = 1.f / (1.f + expf(-(gz[rr][c] + acc[0][j] + bz[c])));
                const float rg = 1.f / (1.f + expf(-(gr[rr][c] + acc[1][j] + br_[c])));
                const float th = tanhf(gh[rr][c] + rg * (acc[2][j] + bh_[c]));
                hn[c] = zz * hp[rr][c] + (1.f - zz) * th;
                hp[rr][c] = hn[c];
            }
            float2 o; o.x = hn[0]; o.y = hn[1];
            *(float2*)yp[rr] = o;

            const int hr = brow + rr * 8;
            __nv_bfloat16 h0 = __float2bfloat16(hn[0]);
            __nv_bfloat16 h1 = __float2bfloat16(hn[1]);
            __nv_bfloat162 hi2; hi2.x = h0; hi2.y = h1;
            __nv_bfloat162 lo2;
            lo2.x = __float2bfloat16(hn[0] - __bfloat162float(h0));
            lo2.y = __float2bfloat16(hn[1] - __bfloat162float(h1));
            *(__nv_bfloat162*)(nhhi + (size_t)hr * UU + uc) = hi2;
            *(__nv_bfloat162*)(nhlo + (size_t)hr * UU + uc) = lo2;

            if (t == TT - 1) {
                *(float2*)(stOut + (size_t)hr * UU + uc) = o;
            }
            gxp[rr] += GG;
            yp[rr]  += UU;
        }

        grid_sync();
    }
}

// ================= host orchestration ========================================
extern "C" void kernel_launch(void* const* d_in, const int* in_sizes, int n_in,
                              void* d_out, int out_size)
{
    const float* inputs = (const float*)d_in[0];
    const float *st[3], *W[3], *Ur[3], *bb[3];

    if (in_sizes[2] == BSZ * UU) {
        st[0] = (const float*)d_in[1];
        st[1] = (const float*)d_in[2];
        st[2] = (const float*)d_in[3];
        for (int l = 0; l < 3; l++) {
            W[l]  = (const float*)d_in[4 + 3*l];
            Ur[l] = (const float*)d_in[5 + 3*l];
            bb[l] = (const float*)d_in[6 + 3*l];
        }
    } else {
        for (int l = 0; l < 3; l++) {
            st[l] = (const float*)d_in[1 + 4*l];
            W[l]  = (const float*)d_in[2 + 4*l];
            Ur[l] = (const float*)d_in[3 + 4*l];
            bb[l] = (const float*)d_in[4 + 4*l];
        }
    }

    float* out = (float*)d_out;
    float *gx, *y0, *y1;
    __nv_bfloat16 *xhi, *xlo, *wthi, *wtlo, *urthi, *urtlo;
    cudaGetSymbolAddress((void**)&gx,    g_gx);
    cudaGetSymbolAddress((void**)&y0,    g_y0);
    cudaGetSymbolAddress((void**)&y1,    g_y1);
    cudaGetSymbolAddress((void**)&xhi,   g_xhi);
    cudaGetSymbolAddress((void**)&xlo,   g_xlo);
    cudaGetSymbolAddress((void**)&wthi,  g_wthi);
    cudaGetSymbolAddress((void**)&wtlo,  g_wtlo);
    cudaGetSymbolAddress((void**)&urthi, g_urthi);
    cudaGetSymbolAddress((void**)&urtlo, g_urtlo);

    cudaFuncSetAttribute(gemm_tc, cudaFuncAttributeMaxDynamicSharedMemorySize,
                         GEMM_SMEM);
    cudaFuncSetAttribute(gru_recurrent,
                         cudaFuncAttributeMaxDynamicSharedMemorySize, REC_SMEM);

    const int    KIN[3]  = {FF, UU, UU};
    const float* xin[3]  = {inputs, y0, y1};
    float*       yout[3] = {y0, y1, out};
    float*       stout   = out + (size_t)MIN_ * UU;

    for (int l = 0; l < 3; l++) {
        const int K = KIN[l];
        split_x<<<(MIN_ * K + 255)/256, 256>>>(xin[l], xhi, xlo, MIN_ * K);
        transpose_split<<<dim3(GG/32, K/32), dim3(32, 8)>>>(W[l], wthi, wtlo, K);
        gemm_tc<<<dim3(GG/128, MIN_/128), 256, GEMM_SMEM>>>(xhi, xlo, wthi, wtlo,
                                                            bb[l], gx, K);
        transpose_split<<<dim3(GG/32, UU/32), dim3(32, 8)>>>(Ur[l], urthi, urtlo, UU);
        split_state<<<(BSZ*UU + 255)/256, 256>>>(st[l]);
        gru_recurrent<<<RBLK, 128, REC_SMEM>>>(gx, bb[l] + GG, st[l],
                                               yout[l], stout + l * BSZ * UU);
    }
}

// round 6
// speedup vs baseline: 3.2797x; 1.1064x over previous
#include <cuda_runtime.h>
#include <cuda_bf16.h>
#include <math.h>
#include <stdint.h>

#define BSZ 64
#define TT  256
#define FF  256
#define UU  1024
#define GG  3072
#define MIN_ (BSZ*TT)

#define RBLK 128          // persistent blocks (1 per SM)

// ---------------- scratch (static device memory) -----------------------------
__device__ float g_gx[(size_t)MIN_ * GG];
__device__ float g_y0[(size_t)MIN_ * UU];
__device__ float g_y1[(size_t)MIN_ * UU];

__device__ __align__(16) __nv_bfloat16 g_xhi[(size_t)MIN_ * UU];
__device__ __align__(16) __nv_bfloat16 g_xlo[(size_t)MIN_ * UU];
__device__ __align__(16) __nv_bfloat16 g_wthi[(size_t)GG * UU];   // W^T
__device__ __align__(16) __nv_bfloat16 g_wtlo[(size_t)GG * UU];
__device__ __align__(16) __nv_bfloat16 g_urthi[(size_t)GG * UU];  // Ur^T
__device__ __align__(16) __nv_bfloat16 g_urtlo[(size_t)GG * UU];
__device__ __align__(16) __nv_bfloat16 g_hhi[2 * BSZ * UU];       // ping-pong h
__device__ __align__(16) __nv_bfloat16 g_hlo[2 * BSZ * UU];

__device__ unsigned g_bar_count = 0;   // monotonic
__device__ unsigned g_bar_phase = 0;   // monotonic

// ================= warp-MMA helpers ==========================================
__device__ __forceinline__ uint32_t smem_to_u32(const void* p) {
    uint32_t a;
    asm("{ .reg .u64 t; cvta.to.shared.u64 t, %1; cvt.u32.u64 %0, t; }"
        : "=r"(a) : "l"(p));
    return a;
}
#define SW128(x) ((x) ^ (((x) >> 3) & 0x70))

__device__ __forceinline__ void ldsm_x4(uint32_t (&r)[4], uint32_t addr) {
    asm volatile("ldmatrix.sync.aligned.m8n8.x4.shared.b16 {%0,%1,%2,%3}, [%4];"
                 : "=r"(r[0]), "=r"(r[1]), "=r"(r[2]), "=r"(r[3]) : "r"(addr));
}
__device__ __forceinline__ void mma_bf16(float (&c)[4], const uint32_t (&a)[4],
                                         uint32_t b0, uint32_t b1) {
    asm volatile(
        "mma.sync.aligned.m16n8k16.row.col.f32.bf16.bf16.f32 "
        "{%0,%1,%2,%3}, {%4,%5,%6,%7}, {%8,%9}, {%0,%1,%2,%3};"
        : "+f"(c[0]), "+f"(c[1]), "+f"(c[2]), "+f"(c[3])
        : "r"(a[0]), "r"(a[1]), "r"(a[2]), "r"(a[3]), "r"(b0), "r"(b1));
}
__device__ __forceinline__ void cp_async16(uint32_t saddr, const void* g) {
    asm volatile("cp.async.cg.shared.global [%0], [%1], 16;"
                 :: "r"(saddr), "l"(g));
}
#define CP_COMMIT() asm volatile("cp.async.commit_group;" ::: "memory")
#define CP_WAIT(n)  asm volatile("cp.async.wait_group %0;" :: "n"(n) : "memory")
#define WG_BAR(id)  asm volatile("bar.sync %0, 128;" :: "r"(id) : "memory")

// ================= input projection GEMM (proven in R4/R5) ===================
#define KC 64
#define OFF_AHI 0
#define OFF_ALO (16*1024)
#define OFF_BHI (32*1024)
#define OFF_BLO (48*1024)
#define BUF_SZ  (64*1024)
#define GEMM_SMEM (2*BUF_SZ)

__launch_bounds__(256, 1)
__global__ void gemm_tc(const __nv_bfloat16* __restrict__ Ahi,
                        const __nv_bfloat16* __restrict__ Alo,
                        const __nv_bfloat16* __restrict__ Bhi,
                        const __nv_bfloat16* __restrict__ Blo,
                        const float* __restrict__ bias,
                        float* __restrict__ C,
                        int K)
{
    extern __shared__ char sm[];
    const uint32_t smb = smem_to_u32(sm);
    const int tid  = threadIdx.x;
    const int wid  = tid >> 5;
    const int lane = tid & 31;
    const int wm   = wid >> 2;
    const int wn   = wid & 3;
    const int row0 = blockIdx.y * 128;
    const int col0 = blockIdx.x * 128;

    float acc[4][4][4];
    #pragma unroll
    for (int mt = 0; mt < 4; mt++)
        #pragma unroll
        for (int nt = 0; nt < 4; nt++)
            #pragma unroll
            for (int j = 0; j < 4; j++) acc[mt][nt][j] = 0.f;

    const int ns = K / KC;

    auto load_chunk = [&](int s) {
        const int b = s & 1;
        const uint32_t bufb = smb + b * BUF_SZ;
        const int k0 = s * KC;
        #pragma unroll 2
        for (int i = tid; i < 1024; i += 256) {
            int r = i >> 3, j = i & 7;
            size_t go = (size_t)(row0 + r) * K + k0 + j * 8;
            uint32_t so = SW128(r * 128 + j * 16);
            cp_async16(bufb + OFF_AHI + so, Ahi + go);
            cp_async16(bufb + OFF_ALO + so, Alo + go);
        }
        #pragma unroll 2
        for (int i = tid; i < 1024; i += 256) {
            int n = i >> 3, j = i & 7;
            size_t go = (size_t)(col0 + n) * K + k0 + j * 8;
            uint32_t so = SW128(n * 128 + j * 16);
            cp_async16(bufb + OFF_BHI + so, Bhi + go);
            cp_async16(bufb + OFF_BLO + so, Blo + go);
        }
        CP_COMMIT();
    };

    load_chunk(0);

    for (int s = 0; s < ns; s++) {
        if (s + 1 < ns) { load_chunk(s + 1); CP_WAIT(1); }
        else            { CP_WAIT(0); }
        __syncthreads();

        const uint32_t bufb = smb + (s & 1) * BUF_SZ;

        #pragma unroll
        for (int k16 = 0; k16 < 4; k16++) {
            const int kc = k16 * 16 + ((lane >> 4) << 3);
            uint32_t ahi[4][4], alo[4][4];
            #pragma unroll
            for (int mt = 0; mt < 4; mt++) {
                const int r = wm * 64 + mt * 16 + (lane & 15);
                const uint32_t so = SW128(r * 128 + kc * 2);
                ldsm_x4(ahi[mt], bufb + OFF_AHI + so);
                ldsm_x4(alo[mt], bufb + OFF_ALO + so);
            }
            #pragma unroll
            for (int bg = 0; bg < 2; bg++) {
                const int n = wn * 32 + bg * 16 + ((lane & 16) >> 1) + (lane & 7);
                const int kcb = k16 * 16 + ((lane & 8) ? 8 : 0);
                const uint32_t so = SW128(n * 128 + kcb * 2);
                uint32_t bhi[4], blo[4];
                ldsm_x4(bhi, bufb + OFF_BHI + so);
                ldsm_x4(blo, bufb + OFF_BLO + so);
                #pragma unroll
                for (int mt = 0; mt < 4; mt++) {
                    mma_bf16(acc[mt][bg*2+0], ahi[mt], bhi[0], bhi[1]);
                    mma_bf16(acc[mt][bg*2+0], ahi[mt], blo[0], blo[1]);
                    mma_bf16(acc[mt][bg*2+0], alo[mt], bhi[0], bhi[1]);
                    mma_bf16(acc[mt][bg*2+1], ahi[mt], bhi[2], bhi[3]);
                    mma_bf16(acc[mt][bg*2+1], ahi[mt], blo[2], blo[3]);
                    mma_bf16(acc[mt][bg*2+1], alo[mt], bhi[2], bhi[3]);
                }
            }
        }
        __syncthreads();
    }

    #pragma unroll
    for (int mt = 0; mt < 4; mt++) {
        const int row = row0 + wm * 64 + mt * 16 + (lane >> 2);
        #pragma unroll
        for (int nt = 0; nt < 4; nt++) {
            const int col = col0 + wn * 32 + nt * 8 + 2 * (lane & 3);
            const float2 bv = *(const float2*)(bias + col);
            float2 v0, v1;
            v0.x = acc[mt][nt][0] + bv.x;  v0.y = acc[mt][nt][1] + bv.y;
            v1.x = acc[mt][nt][2] + bv.x;  v1.y = acc[mt][nt][3] + bv.y;
            *(float2*)(C + (size_t)row * GG + col)       = v0;
            *(float2*)(C + (size_t)(row + 8) * GG + col) = v1;
        }
    }
}

// ================= conversion kernels =========================================
__global__ void split_x(const float* __restrict__ x,
                        __nv_bfloat16* __restrict__ hi,
                        __nv_bfloat16* __restrict__ lo, int n)
{
    int i = blockIdx.x * 256 + threadIdx.x;
    if (i < n) {
        float v = x[i];
        __nv_bfloat16 h = __float2bfloat16(v);
        hi[i] = h;
        lo[i] = __float2bfloat16(v - __bfloat162float(h));
    }
}

__global__ void transpose_split(const float* __restrict__ W,   // [K x 3072]
                                __nv_bfloat16* __restrict__ Th, // [3072 x K]
                                __nv_bfloat16* __restrict__ Tl,
                                int K)
{
    __shared__ float tile[32][33];
    const int nt = blockIdx.x * 32;
    const int kt = blockIdx.y * 32;
    const int tx = threadIdx.x, ty = threadIdx.y;
    #pragma unroll
    for (int r = 0; r < 32; r += 8)
        tile[ty + r][tx] = W[(size_t)(kt + ty + r) * GG + nt + tx];
    __syncthreads();
    #pragma unroll
    for (int r = 0; r < 32; r += 8) {
        float v = tile[tx][ty + r];
        __nv_bfloat16 h = __float2bfloat16(v);
        size_t o = (size_t)(nt + ty + r) * K + kt + tx;
        Th[o] = h;
        Tl[o] = __float2bfloat16(v - __bfloat162float(h));
    }
}

__global__ void split_state(const float* __restrict__ st)
{
    int i = blockIdx.x * 256 + threadIdx.x;
    if (i < BSZ * UU) {
        float v = st[i];
        __nv_bfloat16 h = __float2bfloat16(v);
        g_hhi[i] = h;
        g_hlo[i] = __float2bfloat16(v - __bfloat162float(h));
    }
}

// ================= persistent tensor-core recurrent kernel ===================
// 128 blocks x 256 threads (8 warps, 2 warp-groups splitting K).
// Block = (mhalf: 32 rows) x (utile: 16 u). Ur^T slice hi+lo cached in SMEM.
#define SM_B 0            // 192KB: [term 98304][n(48) 2048B rows]
#define SM_A 196608       // 32KB:  [wg 16384][buf 8192][term 4096][r 128B]
#define SM_RED (SM_A + 16384)   // reduction reuses wg1's A region
#define REC_SMEM 229376

__launch_bounds__(256, 1)
__global__ void gru_recurrent(const float* __restrict__ gx,
                              const float* __restrict__ brec,
                              const float* __restrict__ st,
                              float* __restrict__ y,
                              float* __restrict__ stOut)
{
    extern __shared__ char sm[];
    const uint32_t smb = smem_to_u32(sm);
    const int tid  = threadIdx.x;
    const int wg   = tid >> 7;               // 0,1 : K halves
    const int wtid = tid & 127;
    const int lane = tid & 31;
    const int w4   = (tid >> 5) & 3;
    const int wm   = w4 >> 1;                // 16-row half
    const int wn   = w4 & 1;                 // 8-u half
    const int mhalf = blockIdx.x & 1;
    const int utile = blockIdx.x >> 1;
    const int row0  = mhalf * 32;
    const int u0    = utile * 16;

    // barrier bases (monotonic across launches/replays)
    unsigned base_phase = 0, base_count = 0;
    if (tid == 0) {
        base_phase = *(volatile unsigned*)&g_bar_phase;
        base_count = *(volatile unsigned*)&g_bar_count;
    }

    // ---- fill B SMEM once: 48 rows x 1024 k, hi+lo ----
    for (int g = tid; g < 12288; g += 256) {
        int term = g / 6144, idx = g % 6144;
        int n = idx >> 7, g16 = idx & 127;
        int wng = n / 24, rem = n % 24, gate = rem >> 3, i = rem & 7;
        int urow = gate * 1024 + u0 + wng * 8 + i;
        const __nv_bfloat16* src =
            (term ? g_urtlo : g_urthi) + (size_t)urow * UU + g16 * 8;
        uint32_t so = SM_B + (uint32_t)term * 98304u + (uint32_t)n * 2048u +
                      (((uint32_t)g16 * 16u) ^ (((uint32_t)(n & 7)) << 4));
        cp_async16(smb + so, src);
    }
    CP_COMMIT();
    CP_WAIT(0);
    __syncthreads();

    // ---- per-thread constants (gate math lives in wg0) ----
    const int brow = row0 + wm * 16 + (lane >> 2);
    const int uc   = u0 + wn * 8 + 2 * (lane & 3);

    float bz[2], br_[2], bh_[2], hp[2][2];
    const float* gxp[2];
    float* yp[2];
    if (wg == 0) {
        { float2 v = *(const float2*)(brec + uc);        bz[0]=v.x; bz[1]=v.y; }
        { float2 v = *(const float2*)(brec + 1024 + uc); br_[0]=v.x; br_[1]=v.y; }
        { float2 v = *(const float2*)(brec + 2048 + uc); bh_[0]=v.x; bh_[1]=v.y; }
        { float2 v = *(const float2*)(st + (size_t)brow * UU + uc);
          hp[0][0]=v.x; hp[0][1]=v.y; }
        { float2 v = *(const float2*)(st + (size_t)(brow+8) * UU + uc);
          hp[1][0]=v.x; hp[1][1]=v.y; }
        gxp[0] = gx + (size_t)brow * TT * GG;
        gxp[1] = gx + (size_t)(brow + 8) * TT * GG;
        yp[0] = y + (size_t)brow * TT * UU + uc;
        yp[1] = y + (size_t)(brow + 8) * TT * UU + uc;
    }

    const int barid = 1 + wg;

    // ---- per-wg A chunk fill: 32 rows x 64 k, hi+lo (8KB) ----
    auto fillA = [&](int ck, const __nv_bfloat16* hhi, const __nv_bfloat16* hlo) {
        const int k0 = wg * 512 + ck * 64;
        #pragma unroll
        for (int j = 0; j < 4; j++) {
            int g = wtid + j * 128;               // 0..511
            int term = g >> 8;
            int idx  = g & 255;
            int r = idx >> 3, g16 = idx & 7;
            const __nv_bfloat16* src =
                (term ? hlo : hhi) + (size_t)(row0 + r) * UU + k0 + g16 * 8;
            uint32_t so = SM_A + (uint32_t)wg * 16384u + (uint32_t)(ck & 1) * 8192u +
                          (uint32_t)term * 4096u + (uint32_t)r * 128u +
                          (((uint32_t)g16 * 16u) ^ (((uint32_t)(r & 7)) << 4));
            cp_async16(smb + so, src);
        }
        CP_COMMIT();
    };

    for (int t = 0; t < TT; t++) {
        const __nv_bfloat16* hhi = g_hhi + (t & 1) * (BSZ * UU);
        const __nv_bfloat16* hlo = g_hlo + (t & 1) * (BSZ * UU);
        __nv_bfloat16* nhhi = g_hhi + ((t + 1) & 1) * (BSZ * UU);
        __nv_bfloat16* nhlo = g_hlo + ((t + 1) & 1) * (BSZ * UU);

        fillA(0, hhi, hlo);
        fillA(1, hhi, hlo);

        // prefetch this step's gx operands (wg0)
        float gz[2][2], gr[2][2], gh[2][2];
        if (wg == 0) {
            #pragma unroll
            for (int rr = 0; rr < 2; rr++) {
                const float* gq = gxp[rr];
                float2 v;
                v = *(const float2*)(gq + uc);        gz[rr][0]=v.x; gz[rr][1]=v.y;
                v = *(const float2*)(gq + 1024 + uc); gr[rr][0]=v.x; gr[rr][1]=v.y;
                v = *(const float2*)(gq + 2048 + uc); gh[rr][0]=v.x; gh[rr][1]=v.y;
            }
        }

        float acc[3][4], acc2[3][4];
        #pragma unroll
        for (int g = 0; g < 3; g++)
            #pragma unroll
            for (int j = 0; j < 4; j++) { acc[g][j] = 0.f; acc2[g][j] = 0.f; }

        #pragma unroll 1
        for (int ck = 0; ck < 8; ck++) {
            if (ck < 7) { CP_WAIT(1); } else { CP_WAIT(0); }
            WG_BAR(barid);

            const uint32_t Ab = smb + SM_A + (uint32_t)wg * 16384u +
                                (uint32_t)(ck & 1) * 8192u;
            const uint32_t kbB = (uint32_t)(wg * 1024 + ck * 128);   // bytes

            #pragma unroll
            for (int k32 = 0; k32 < 2; k32++) {
                uint32_t bh4[3][4], bl4[3][4];
                #pragma unroll
                for (int g = 0; g < 3; g++) {
                    uint32_t n  = (uint32_t)(wn * 24 + g * 8 + (lane & 7));
                    uint32_t kb = kbB + (uint32_t)k32 * 64u +
                                  (uint32_t)((lane >> 3) & 3) * 16u;
                    uint32_t so = SM_B + n * 2048u + (kb ^ ((n & 7u) << 4));
                    ldsm_x4(bh4[g], smb + so);
                    ldsm_x4(bl4[g], smb + so + 98304u);
                }
                #pragma unroll
                for (int hf = 0; hf < 2; hf++) {
                    uint32_t ah[4], al[4];
                    uint32_t r  = (uint32_t)(wm * 16 + (lane & 15));
                    uint32_t kb = (uint32_t)k32 * 64u + (uint32_t)hf * 32u +
                                  (uint32_t)(lane >> 4) * 16u;
                    uint32_t so = Ab + r * 128u + (kb ^ ((r & 7u) << 4));
                    ldsm_x4(ah, so);
                    ldsm_x4(al, so + 4096u);
                    #pragma unroll
                    for (int g = 0; g < 3; g++) {
                        mma_bf16(acc[g],  ah, bh4[g][hf*2], bh4[g][hf*2+1]);
                        mma_bf16(acc2[g], ah, bl4[g][hf*2], bl4[g][hf*2+1]);
                        mma_bf16(acc2[g], al, bh4[g][hf*2], bh4[g][hf*2+1]);
                    }
                }
            }
            WG_BAR(barid);
            if (ck + 2 < 8) fillA(ck + 2, hhi, hlo);
        }

        // ---- cross-wg reduction + gates ----
        #pragma unroll
        for (int g = 0; g < 3; g++)
            #pragma unroll
            for (int j = 0; j < 4; j++) acc[g][j] += acc2[g][j];

        float* red = (float*)(sm + SM_RED);
        if (wg == 1) {
            #pragma unroll
            for (int g = 0; g < 3; g++)
                #pragma unroll
                for (int j = 0; j < 4; j++)
                    red[wtid * 12 + g * 4 + j] = acc[g][j];
        }
        __syncthreads();

        if (wg == 0) {
            #pragma unroll
            for (int g = 0; g < 3; g++)
                #pragma unroll
                for (int j = 0; j < 4; j++)
                    acc[g][j] += red[wtid * 12 + g * 4 + j];

            #pragma unroll
            for (int rr = 0; rr < 2; rr++) {
                float hn[2];
                #pragma unroll
                for (int c = 0; c < 2; c++) {
                    const int j = rr * 2 + c;
                    const float zz = 1.f / (1.f + expf(-(gz[rr][c] + acc[0][j] + bz[c])));
                    const float rg = 1.f / (1.f + expf(-(gr[rr][c] + acc[1][j] + br_[c])));
                    const float th = tanhf(gh[rr][c] + rg * (acc[2][j] + bh_[c]));
                    hn[c] = zz * hp[rr][c] + (1.f - zz) * th;
                    hp[rr][c] = hn[c];
                }
                float2 o; o.x = hn[0]; o.y = hn[1];
                *(float2*)yp[rr] = o;

                const int hr = brow + rr * 8;
                __nv_bfloat16 h0 = __float2bfloat16(hn[0]);
                __nv_bfloat16 h1 = __float2bfloat16(hn[1]);
                __nv_bfloat162 hi2; hi2.x = h0; hi2.y = h1;
                __nv_bfloat162 lo2;
                lo2.x = __float2bfloat16(hn[0] - __bfloat162float(h0));
                lo2.y = __float2bfloat16(hn[1] - __bfloat162float(h1));
                *(__nv_bfloat162*)(nhhi + (size_t)hr * UU + uc) = hi2;
                *(__nv_bfloat162*)(nhlo + (size_t)hr * UU + uc) = lo2;

                if (t == TT - 1) {
                    *(float2*)(stOut + (size_t)hr * UU + uc) = o;
                }
                gxp[rr] += GG;
                yp[rr]  += UU;
            }
        }

        // ---- grid barrier (skip after last step) ----
        if (t + 1 < TT) {
            __syncthreads();
            if (tid == 0) {
                __threadfence();
                unsigned a = atomicAdd(&g_bar_count, 1u) + 1u;
                unsigned target = base_count + (unsigned)(t + 1) * (unsigned)RBLK;
                unsigned gen    = base_phase + (unsigned)(t + 1);
                if ((int)(a - target) == 0) {
                    atomicExch(&g_bar_phase, gen);
                } else {
                    volatile unsigned* ph = &g_bar_phase;
                    while ((int)(*ph - gen) < 0) { }
                }
                __threadfence();
            }
            __syncthreads();
        }
    }
}

// ================= host orchestration ========================================
extern "C" void kernel_launch(void* const* d_in, const int* in_sizes, int n_in,
                              void* d_out, int out_size)
{
    const float* inputs = (const float*)d_in[0];
    const float *st[3], *W[3], *Ur[3], *bb[3];

    if (in_sizes[2] == BSZ * UU) {
        st[0] = (const float*)d_in[1];
        st[1] = (const float*)d_in[2];
        st[2] = (const float*)d_in[3];
        for (int l = 0; l < 3; l++) {
            W[l]  = (const float*)d_in[4 + 3*l];
            Ur[l] = (const float*)d_in[5 + 3*l];
            bb[l] = (const float*)d_in[6 + 3*l];
        }
    } else {
        for (int l = 0; l < 3; l++) {
            st[l] = (const float*)d_in[1 + 4*l];
            W[l]  = (const float*)d_in[2 + 4*l];
            Ur[l] = (const float*)d_in[3 + 4*l];
            bb[l] = (const float*)d_in[4 + 4*l];
        }
    }

    float* out = (float*)d_out;
    float *gx, *y0, *y1;
    __nv_bfloat16 *xhi, *xlo, *wthi, *wtlo, *urthi, *urtlo;
    cudaGetSymbolAddress((void**)&gx,    g_gx);
    cudaGetSymbolAddress((void**)&y0,    g_y0);
    cudaGetSymbolAddress((void**)&y1,    g_y1);
    cudaGetSymbolAddress((void**)&xhi,   g_xhi);
    cudaGetSymbolAddress((void**)&xlo,   g_xlo);
    cudaGetSymbolAddress((void**)&wthi,  g_wthi);
    cudaGetSymbolAddress((void**)&wtlo,  g_wtlo);
    cudaGetSymbolAddress((void**)&urthi, g_urthi);
    cudaGetSymbolAddress((void**)&urtlo, g_urtlo);

    cudaFuncSetAttribute(gemm_tc, cudaFuncAttributeMaxDynamicSharedMemorySize,
                         GEMM_SMEM);
    cudaFuncSetAttribute(gru_recurrent,
                         cudaFuncAttributeMaxDynamicSharedMemorySize, REC_SMEM);

    const int    KIN[3]  = {FF, UU, UU};
    const float* xin[3]  = {inputs, y0, y1};
    float*       yout[3] = {y0, y1, out};
    float*       stout   = out + (size_t)MIN_ * UU;

    for (int l = 0; l < 3; l++) {
        const int K = KIN[l];
        split_x<<<(MIN_ * K + 255)/256, 256>>>(xin[l], xhi, xlo, MIN_ * K);
        transpose_split<<<dim3(GG/32, K/32), dim3(32, 8)>>>(W[l], wthi, wtlo, K);
        gemm_tc<<<dim3(GG/128, MIN_/128), 256, GEMM_SMEM>>>(xhi, xlo, wthi, wtlo,
                                                            bb[l], gx, K);
        transpose_split<<<dim3(GG/32, UU/32), dim3(32, 8)>>>(Ur[l], urthi, urtlo, UU);
        split_state<<<(BSZ*UU + 255)/256, 256>>>(st[l]);
        gru_recurrent<<<RBLK, 256, REC_SMEM>>>(gx, bb[l] + GG, st[l],
                                               yout[l], stout + l * BSZ * UU);
    }
}

// round 7
// speedup vs baseline: 3.3370x; 1.0175x over previous
#include <cuda_runtime.h>
#include <cuda_bf16.h>
#include <math.h>
#include <stdint.h>

#define BSZ 64
#define TT  256
#define FF  256
#define UU  1024
#define GG  3072
#define MIN_ (BSZ*TT)

#define RBLK 128          // persistent blocks (1 per SM)

// ---------------- scratch (static device memory) -----------------------------
__device__ float g_gx[(size_t)MIN_ * GG];
__device__ float g_y0[(size_t)MIN_ * UU];
__device__ float g_y1[(size_t)MIN_ * UU];

__device__ __align__(16) __nv_bfloat16 g_xhi[(size_t)MIN_ * UU];
__device__ __align__(16) __nv_bfloat16 g_xlo[(size_t)MIN_ * UU];
__device__ __align__(16) __nv_bfloat16 g_wthi[(size_t)GG * UU];   // W^T
__device__ __align__(16) __nv_bfloat16 g_wtlo[(size_t)GG * UU];
__device__ __align__(16) __nv_bfloat16 g_urthi[(size_t)GG * UU];  // Ur^T
__device__ __align__(16) __nv_bfloat16 g_urtlo[(size_t)GG * UU];
__device__ __align__(16) __nv_bfloat16 g_hhi[2 * BSZ * UU];       // ping-pong h
__device__ __align__(16) __nv_bfloat16 g_hlo[2 * BSZ * UU];

// per-block monotonic flags, one 128B line each (no RMW serialization)
__device__ __align__(128) unsigned g_flags[RBLK * 32];

// ================= warp-MMA helpers ==========================================
__device__ __forceinline__ uint32_t smem_to_u32(const void* p) {
    uint32_t a;
    asm("{ .reg .u64 t; cvta.to.shared.u64 t, %1; cvt.u32.u64 %0, t; }"
        : "=r"(a) : "l"(p));
    return a;
}
#define SW128(x) ((x) ^ (((x) >> 3) & 0x70))

__device__ __forceinline__ void ldsm_x4(uint32_t (&r)[4], uint32_t addr) {
    asm volatile("ldmatrix.sync.aligned.m8n8.x4.shared.b16 {%0,%1,%2,%3}, [%4];"
                 : "=r"(r[0]), "=r"(r[1]), "=r"(r[2]), "=r"(r[3]) : "r"(addr));
}
__device__ __forceinline__ void mma_bf16(float (&c)[4], const uint32_t (&a)[4],
                                         uint32_t b0, uint32_t b1) {
    asm volatile(
        "mma.sync.aligned.m16n8k16.row.col.f32.bf16.bf16.f32 "
        "{%0,%1,%2,%3}, {%4,%5,%6,%7}, {%8,%9}, {%0,%1,%2,%3};"
        : "+f"(c[0]), "+f"(c[1]), "+f"(c[2]), "+f"(c[3])
        : "r"(a[0]), "r"(a[1]), "r"(a[2]), "r"(a[3]), "r"(b0), "r"(b1));
}
__device__ __forceinline__ void cp_async16(uint32_t saddr, const void* g) {
    asm volatile("cp.async.cg.shared.global [%0], [%1], 16;"
                 :: "r"(saddr), "l"(g));
}
#define CP_COMMIT() asm volatile("cp.async.commit_group;" ::: "memory")
#define CP_WAIT(n)  asm volatile("cp.async.wait_group %0;" :: "n"(n) : "memory")
#define WG_BAR(id)  asm volatile("bar.sync %0, 128;" :: "r"(id) : "memory")

// ================= input projection GEMM (proven in R4/R5) ===================
#define KC 64
#define OFF_AHI 0
#define OFF_ALO (16*1024)
#define OFF_BHI (32*1024)
#define OFF_BLO (48*1024)
#define BUF_SZ  (64*1024)
#define GEMM_SMEM (2*BUF_SZ)

__launch_bounds__(256, 1)
__global__ void gemm_tc(const __nv_bfloat16* __restrict__ Ahi,
                        const __nv_bfloat16* __restrict__ Alo,
                        const __nv_bfloat16* __restrict__ Bhi,
                        const __nv_bfloat16* __restrict__ Blo,
                        const float* __restrict__ bias,
                        float* __restrict__ C,
                        int K)
{
    extern __shared__ char sm[];
    const uint32_t smb = smem_to_u32(sm);
    const int tid  = threadIdx.x;
    const int wid  = tid >> 5;
    const int lane = tid & 31;
    const int wm   = wid >> 2;
    const int wn   = wid & 3;
    const int row0 = blockIdx.y * 128;
    const int col0 = blockIdx.x * 128;

    float acc[4][4][4];
    #pragma unroll
    for (int mt = 0; mt < 4; mt++)
        #pragma unroll
        for (int nt = 0; nt < 4; nt++)
            #pragma unroll
            for (int j = 0; j < 4; j++) acc[mt][nt][j] = 0.f;

    const int ns = K / KC;

    auto load_chunk = [&](int s) {
        const int b = s & 1;
        const uint32_t bufb = smb + b * BUF_SZ;
        const int k0 = s * KC;
        #pragma unroll 2
        for (int i = tid; i < 1024; i += 256) {
            int r = i >> 3, j = i & 7;
            size_t go = (size_t)(row0 + r) * K + k0 + j * 8;
            uint32_t so = SW128(r * 128 + j * 16);
            cp_async16(bufb + OFF_AHI + so, Ahi + go);
            cp_async16(bufb + OFF_ALO + so, Alo + go);
        }
        #pragma unroll 2
        for (int i = tid; i < 1024; i += 256) {
            int n = i >> 3, j = i & 7;
            size_t go = (size_t)(col0 + n) * K + k0 + j * 8;
            uint32_t so = SW128(n * 128 + j * 16);
            cp_async16(bufb + OFF_BHI + so, Bhi + go);
            cp_async16(bufb + OFF_BLO + so, Blo + go);
        }
        CP_COMMIT();
    };

    load_chunk(0);

    for (int s = 0; s < ns; s++) {
        if (s + 1 < ns) { load_chunk(s + 1); CP_WAIT(1); }
        else            { CP_WAIT(0); }
        __syncthreads();

        const uint32_t bufb = smb + (s & 1) * BUF_SZ;

        #pragma unroll
        for (int k16 = 0; k16 < 4; k16++) {
            const int kc = k16 * 16 + ((lane >> 4) << 3);
            uint32_t ahi[4][4], alo[4][4];
            #pragma unroll
            for (int mt = 0; mt < 4; mt++) {
                const int r = wm * 64 + mt * 16 + (lane & 15);
                const uint32_t so = SW128(r * 128 + kc * 2);
                ldsm_x4(ahi[mt], bufb + OFF_AHI + so);
                ldsm_x4(alo[mt], bufb + OFF_ALO + so);
            }
            #pragma unroll
            for (int bg = 0; bg < 2; bg++) {
                const int n = wn * 32 + bg * 16 + ((lane & 16) >> 1) + (lane & 7);
                const int kcb = k16 * 16 + ((lane & 8) ? 8 : 0);
                const uint32_t so = SW128(n * 128 + kcb * 2);
                uint32_t bhi[4], blo[4];
                ldsm_x4(bhi, bufb + OFF_BHI + so);
                ldsm_x4(blo, bufb + OFF_BLO + so);
                #pragma unroll
                for (int mt = 0; mt < 4; mt++) {
                    mma_bf16(acc[mt][bg*2+0], ahi[mt], bhi[0], bhi[1]);
                    mma_bf16(acc[mt][bg*2+0], ahi[mt], blo[0], blo[1]);
                    mma_bf16(acc[mt][bg*2+0], alo[mt], bhi[0], bhi[1]);
                    mma_bf16(acc[mt][bg*2+1], ahi[mt], bhi[2], bhi[3]);
                    mma_bf16(acc[mt][bg*2+1], ahi[mt], blo[2], blo[3]);
                    mma_bf16(acc[mt][bg*2+1], alo[mt], bhi[2], bhi[3]);
                }
            }
        }
        __syncthreads();
    }

    #pragma unroll
    for (int mt = 0; mt < 4; mt++) {
        const int row = row0 + wm * 64 + mt * 16 + (lane >> 2);
        #pragma unroll
        for (int nt = 0; nt < 4; nt++) {
            const int col = col0 + wn * 32 + nt * 8 + 2 * (lane & 3);
            const float2 bv = *(const float2*)(bias + col);
            float2 v0, v1;
            v0.x = acc[mt][nt][0] + bv.x;  v0.y = acc[mt][nt][1] + bv.y;
            v1.x = acc[mt][nt][2] + bv.x;  v1.y = acc[mt][nt][3] + bv.y;
            *(float2*)(C + (size_t)row * GG + col)       = v0;
            *(float2*)(C + (size_t)(row + 8) * GG + col) = v1;
        }
    }
}

// ================= conversion kernels =========================================
__global__ void split_x(const float* __restrict__ x,
                        __nv_bfloat16* __restrict__ hi,
                        __nv_bfloat16* __restrict__ lo, int n)
{
    int i = blockIdx.x * 256 + threadIdx.x;
    if (i < n) {
        float v = x[i];
        __nv_bfloat16 h = __float2bfloat16(v);
        hi[i] = h;
        lo[i] = __float2bfloat16(v - __bfloat162float(h));
    }
}

__global__ void transpose_split(const float* __restrict__ W,   // [K x 3072]
                                __nv_bfloat16* __restrict__ Th, // [3072 x K]
                                __nv_bfloat16* __restrict__ Tl,
                                int K)
{
    __shared__ float tile[32][33];
    const int nt = blockIdx.x * 32;
    const int kt = blockIdx.y * 32;
    const int tx = threadIdx.x, ty = threadIdx.y;
    #pragma unroll
    for (int r = 0; r < 32; r += 8)
        tile[ty + r][tx] = W[(size_t)(kt + ty + r) * GG + nt + tx];
    __syncthreads();
    #pragma unroll
    for (int r = 0; r < 32; r += 8) {
        float v = tile[tx][ty + r];
        __nv_bfloat16 h = __float2bfloat16(v);
        size_t o = (size_t)(nt + ty + r) * K + kt + tx;
        Th[o] = h;
        Tl[o] = __float2bfloat16(v - __bfloat162float(h));
    }
}

__global__ void split_state(const float* __restrict__ st)
{
    int i = blockIdx.x * 256 + threadIdx.x;
    if (i < BSZ * UU) {
        float v = st[i];
        __nv_bfloat16 h = __float2bfloat16(v);
        g_hhi[i] = h;
        g_hlo[i] = __float2bfloat16(v - __bfloat162float(h));
    }
}

// ================= persistent tensor-core recurrent kernel ===================
// 128 blocks x 256 threads (8 warps, 2 warp-groups splitting K).
// Block = (mhalf: 32 rows) x (utile: 16 u). Ur^T slice hi+lo cached in SMEM.
// Cross-block sync: per-block flag lines + half-grid (same-mhalf) waits.
#define SM_B 0            // 192KB: [term 98304][n(48) 2048B rows]
#define SM_A 196608       // 32KB:  [wg 16384][buf 8192][term 4096][r 128B]
#define SM_RED (SM_A + 16384)   // reduction reuses wg1's A region
#define REC_SMEM 229376

__launch_bounds__(256, 1)
__global__ void gru_recurrent(const float* __restrict__ gx,
                              const float* __restrict__ brec,
                              const float* __restrict__ st,
                              float* __restrict__ y,
                              float* __restrict__ stOut,
                              __nv_bfloat16* __restrict__ xh,   // next-layer A hi
                              __nv_bfloat16* __restrict__ xl,   // next-layer A lo
                              int writeX)
{
    extern __shared__ char sm[];
    const uint32_t smb = smem_to_u32(sm);
    const int tid  = threadIdx.x;
    const int wg   = tid >> 7;               // 0,1 : K halves
    const int wtid = tid & 127;
    const int lane = tid & 31;
    const int w4   = (tid >> 5) & 3;
    const int wm   = w4 >> 1;                // 16-row half
    const int wn   = w4 & 1;                 // 8-u half
    const int bid  = blockIdx.x;
    const int mhalf = bid & 1;
    const int utile = bid >> 1;
    const int row0  = mhalf * 32;
    const int u0    = utile * 16;

    // monotonic flag base (own flag — unchanged since our last write)
    const unsigned f0 = *(volatile unsigned*)&g_flags[(size_t)bid * 32];

    // ---- fill B SMEM once: 48 rows x 1024 k, hi+lo ----
    for (int g = tid; g < 12288; g += 256) {
        int term = g / 6144, idx = g % 6144;
        int n = idx >> 7, g16 = idx & 127;
        int wng = n / 24, rem = n % 24, gate = rem >> 3, i = rem & 7;
        int urow = gate * 1024 + u0 + wng * 8 + i;
        const __nv_bfloat16* src =
            (term ? g_urtlo : g_urthi) + (size_t)urow * UU + g16 * 8;
        uint32_t so = SM_B + (uint32_t)term * 98304u + (uint32_t)n * 2048u +
                      (((uint32_t)g16 * 16u) ^ (((uint32_t)(n & 7)) << 4));
        cp_async16(smb + so, src);
    }
    CP_COMMIT();
    CP_WAIT(0);
    __syncthreads();

    // ---- per-thread constants (gate math lives in wg0) ----
    const int brow = row0 + wm * 16 + (lane >> 2);
    const int uc   = u0 + wn * 8 + 2 * (lane & 3);

    float bz[2], br_[2], bh_[2], hp[2][2];
    const float* gxp[2];
    size_t yo[2];
    if (wg == 0) {
        { float2 v = *(const float2*)(brec + uc);        bz[0]=v.x; bz[1]=v.y; }
        { float2 v = *(const float2*)(brec + 1024 + uc); br_[0]=v.x; br_[1]=v.y; }
        { float2 v = *(const float2*)(brec + 2048 + uc); bh_[0]=v.x; bh_[1]=v.y; }
        { float2 v = *(const float2*)(st + (size_t)brow * UU + uc);
          hp[0][0]=v.x; hp[0][1]=v.y; }
        { float2 v = *(const float2*)(st + (size_t)(brow+8) * UU + uc);
          hp[1][0]=v.x; hp[1][1]=v.y; }
        gxp[0] = gx + (size_t)brow * TT * GG;
        gxp[1] = gx + (size_t)(brow + 8) * TT * GG;
        yo[0] = (size_t)brow * TT * UU + uc;
        yo[1] = (size_t)(brow + 8) * TT * UU + uc;
    }

    const int barid = 1 + wg;

    // ---- per-wg A chunk fill: 32 rows x 64 k, hi+lo (8KB) ----
    auto fillA = [&](int ck, const __nv_bfloat16* hhi, const __nv_bfloat16* hlo) {
        const int k0 = wg * 512 + ck * 64;
        #pragma unroll
        for (int j = 0; j < 4; j++) {
            int g = wtid + j * 128;               // 0..511
            int term = g >> 8;
            int idx  = g & 255;
            int r = idx >> 3, g16 = idx & 7;
            const __nv_bfloat16* src =
                (term ? hlo : hhi) + (size_t)(row0 + r) * UU + k0 + g16 * 8;
            uint32_t so = SM_A + (uint32_t)wg * 16384u + (uint32_t)(ck & 1) * 8192u +
                          (uint32_t)term * 4096u + (uint32_t)r * 128u +
                          (((uint32_t)g16 * 16u) ^ (((uint32_t)(r & 7)) << 4));
            cp_async16(smb + so, src);
        }
        CP_COMMIT();
    };

    for (int t = 0; t < TT; t++) {
        const __nv_bfloat16* hhi = g_hhi + (t & 1) * (BSZ * UU);
        const __nv_bfloat16* hlo = g_hlo + (t & 1) * (BSZ * UU);
        __nv_bfloat16* nhhi = g_hhi + ((t + 1) & 1) * (BSZ * UU);
        __nv_bfloat16* nhlo = g_hlo + ((t + 1) & 1) * (BSZ * UU);

        fillA(0, hhi, hlo);
        fillA(1, hhi, hlo);

        // prefetch this step's gx operands (wg0)
        float gz[2][2], gr[2][2], gh[2][2];
        if (wg == 0) {
            #pragma unroll
            for (int rr = 0; rr < 2; rr++) {
                const float* gq = gxp[rr];
                float2 v;
                v = *(const float2*)(gq + uc);        gz[rr][0]=v.x; gz[rr][1]=v.y;
                v = *(const float2*)(gq + 1024 + uc); gr[rr][0]=v.x; gr[rr][1]=v.y;
                v = *(const float2*)(gq + 2048 + uc); gh[rr][0]=v.x; gh[rr][1]=v.y;
            }
        }

        float acc[3][4], acc2[3][4];
        #pragma unroll
        for (int g = 0; g < 3; g++)
            #pragma unroll
            for (int j = 0; j < 4; j++) { acc[g][j] = 0.f; acc2[g][j] = 0.f; }

        #pragma unroll 1
        for (int ck = 0; ck < 8; ck++) {
            if (ck < 7) { CP_WAIT(1); } else { CP_WAIT(0); }
            WG_BAR(barid);

            const uint32_t Ab = smb + SM_A + (uint32_t)wg * 16384u +
                                (uint32_t)(ck & 1) * 8192u;
            const uint32_t kbB = (uint32_t)(wg * 1024 + ck * 128);   // bytes

            #pragma unroll
            for (int k32 = 0; k32 < 2; k32++) {
                uint32_t bh4[3][4], bl4[3][4];
                #pragma unroll
                for (int g = 0; g < 3; g++) {
                    uint32_t n  = (uint32_t)(wn * 24 + g * 8 + (lane & 7));
                    uint32_t kb = kbB + (uint32_t)k32 * 64u +
                                  (uint32_t)((lane >> 3) & 3) * 16u;
                    uint32_t so = SM_B + n * 2048u + (kb ^ ((n & 7u) << 4));
                    ldsm_x4(bh4[g], smb + so);
                    ldsm_x4(bl4[g], smb + so + 98304u);
                }
                #pragma unroll
                for (int hf = 0; hf < 2; hf++) {
                    uint32_t ah[4], al[4];
                    uint32_t r  = (uint32_t)(wm * 16 + (lane & 15));
                    uint32_t kb = (uint32_t)k32 * 64u + (uint32_t)hf * 32u +
                                  (uint32_t)(lane >> 4) * 16u;
                    uint32_t so = Ab + r * 128u + (kb ^ ((r & 7u) << 4));
                    ldsm_x4(ah, so);
                    ldsm_x4(al, so + 4096u);
                    #pragma unroll
                    for (int g = 0; g < 3; g++) {
                        mma_bf16(acc[g],  ah, bh4[g][hf*2], bh4[g][hf*2+1]);
                        mma_bf16(acc2[g], ah, bl4[g][hf*2], bl4[g][hf*2+1]);
                        mma_bf16(acc2[g], al, bh4[g][hf*2], bh4[g][hf*2+1]);
                    }
                }
            }
            WG_BAR(barid);
            if (ck + 2 < 8) fillA(ck + 2, hhi, hlo);
        }

        // ---- cross-wg reduction + gates ----
        #pragma unroll
        for (int g = 0; g < 3; g++)
            #pragma unroll
            for (int j = 0; j < 4; j++) acc[g][j] += acc2[g][j];

        float* red = (float*)(sm + SM_RED);
        if (wg == 1) {
            #pragma unroll
            for (int g = 0; g < 3; g++)
                #pragma unroll
                for (int j = 0; j < 4; j++)
                    red[wtid * 12 + g * 4 + j] = acc[g][j];
        }
        __syncthreads();

        if (wg == 0) {
            #pragma unroll
            for (int g = 0; g < 3; g++)
                #pragma unroll
                for (int j = 0; j < 4; j++)
                    acc[g][j] += red[wtid * 12 + g * 4 + j];

            #pragma unroll
            for (int rr = 0; rr < 2; rr++) {
                float hn[2];
                #pragma unroll
                for (int c = 0; c < 2; c++) {
                    const int j = rr * 2 + c;
                    const float zz = 1.f / (1.f + expf(-(gz[rr][c] + acc[0][j] + bz[c])));
                    const float rg = 1.f / (1.f + expf(-(gr[rr][c] + acc[1][j] + br_[c])));
                    const float th = tanhf(gh[rr][c] + rg * (acc[2][j] + bh_[c]));
                    hn[c] = zz * hp[rr][c] + (1.f - zz) * th;
                    hp[rr][c] = hn[c];
                }
                float2 o; o.x = hn[0]; o.y = hn[1];
                *(float2*)(y + yo[rr]) = o;

                const int hr = brow + rr * 8;
                __nv_bfloat16 h0 = __float2bfloat16(hn[0]);
                __nv_bfloat16 h1 = __float2bfloat16(hn[1]);
                __nv_bfloat162 hi2; hi2.x = h0; hi2.y = h1;
                __nv_bfloat162 lo2;
                lo2.x = __float2bfloat16(hn[0] - __bfloat162float(h0));
                lo2.y = __float2bfloat16(hn[1] - __bfloat162float(h1));
                *(__nv_bfloat162*)(nhhi + (size_t)hr * UU + uc) = hi2;
                *(__nv_bfloat162*)(nhlo + (size_t)hr * UU + uc) = lo2;

                if (writeX) {   // fused split_x for the next layer's GEMM A
                    *(__nv_bfloat162*)(xh + yo[rr]) = hi2;
                    *(__nv_bfloat162*)(xl + yo[rr]) = lo2;
                }
                if (t == TT - 1) {
                    *(float2*)(stOut + (size_t)hr * UU + uc) = o;
                }
                gxp[rr] += GG;
                yo[rr]  += UU;
            }
            __threadfence();   // order h stores before flag release
        }

        // ---- flag-array half-grid barrier (skip after last step) ----
        __syncthreads();
        if (t + 1 < TT) {
            const unsigned tgt = f0 + (unsigned)(t + 1);
            if (tid == 0) {
                asm volatile("st.release.gpu.global.u32 [%0], %1;"
                             :: "l"(g_flags + (size_t)bid * 32), "r"(tgt)
                             : "memory");
            }
            if (tid < 64) {
                const unsigned* pf = g_flags + (size_t)(mhalf + 2 * tid) * 32;
                unsigned v;
                do {
                    asm volatile("ld.acquire.gpu.global.u32 %0, [%1];"
                                 : "=r"(v) : "l"(pf) : "memory");
                } while ((int)(v - tgt) < 0);
            }
            __syncthreads();
        }
    }
}

// ================= host orchestration ========================================
extern "C" void kernel_launch(void* const* d_in, const int* in_sizes, int n_in,
                              void* d_out, int out_size)
{
    const float* inputs = (const float*)d_in[0];
    const float *st[3], *W[3], *Ur[3], *bb[3];

    if (in_sizes[2] == BSZ * UU) {
        st[0] = (const float*)d_in[1];
        st[1] = (const float*)d_in[2];
        st[2] = (const float*)d_in[3];
        for (int l = 0; l < 3; l++) {
            W[l]  = (const float*)d_in[4 + 3*l];
            Ur[l] = (const float*)d_in[5 + 3*l];
            bb[l] = (const float*)d_in[6 + 3*l];
        }
    } else {
        for (int l = 0; l < 3; l++) {
            st[l] = (const float*)d_in[1 + 4*l];
            W[l]  = (const float*)d_in[2 + 4*l];
            Ur[l] = (const float*)d_in[3 + 4*l];
            bb[l] = (const float*)d_in[4 + 4*l];
        }
    }

    float* out = (float*)d_out;
    float *gx, *y0, *y1;
    __nv_bfloat16 *xhi, *xlo, *wthi, *wtlo, *urthi, *urtlo;
    cudaGetSymbolAddress((void**)&gx,    g_gx);
    cudaGetSymbolAddress((void**)&y0,    g_y0);
    cudaGetSymbolAddress((void**)&y1,    g_y1);
    cudaGetSymbolAddress((void**)&xhi,   g_xhi);
    cudaGetSymbolAddress((void**)&xlo,   g_xlo);
    cudaGetSymbolAddress((void**)&wthi,  g_wthi);
    cudaGetSymbolAddress((void**)&wtlo,  g_wtlo);
    cudaGetSymbolAddress((void**)&urthi, g_urthi);
    cudaGetSymbolAddress((void**)&urtlo, g_urtlo);

    cudaFuncSetAttribute(gemm_tc, cudaFuncAttributeMaxDynamicSharedMemorySize,
                         GEMM_SMEM);
    cudaFuncSetAttribute(gru_recurrent,
                         cudaFuncAttributeMaxDynamicSharedMemorySize, REC_SMEM);

    const int    KIN[3]  = {FF, UU, UU};
    float*       yout[3] = {y0, y1, out};
    float*       stout   = out + (size_t)MIN_ * UU;

    for (int l = 0; l < 3; l++) {
        const int K = KIN[l];
        if (l == 0) {   // layers 1,2: xhi/xlo are written by the previous gru
            split_x<<<(MIN_ * K + 255)/256, 256>>>(inputs, xhi, xlo, MIN_ * K);
        }
        transpose_split<<<dim3(GG/32, K/32), dim3(32, 8)>>>(W[l], wthi, wtlo, K);
        gemm_tc<<<dim3(GG/128, MIN_/128), 256, GEMM_SMEM>>>(xhi, xlo, wthi, wtlo,
                                                            bb[l], gx, K);
        transpose_split<<<dim3(GG/32, UU/32), dim3(32, 8)>>>(Ur[l], urthi, urtlo, UU);
        split_state<<<(BSZ*UU + 255)/256, 256>>>(st[l]);
        gru_recurrent<<<RBLK, 256, REC_SMEM>>>(gx, bb[l] + GG, st[l],
                                               yout[l], stout + l * BSZ * UU,
                                               xhi, xlo, (l < 2) ? 1 : 0);
    }
}